// round 1
// baseline (speedup 1.0000x reference)
#include <cuda_runtime.h>
#include <math.h>

#define D_MODEL 2048
#define N_HEADS 16
#define D_HEAD  128
#define B_      4
#define T_      2048
#define M_TOTAL (B_*T_)   // 8192

// Scratch: __device__ globals (no allocation allowed in kernel_launch).
__device__ float g_q [B_*T_*D_MODEL];
__device__ float g_k [B_*T_*D_MODEL];
__device__ float g_v [B_*T_*D_MODEL];
__device__ float g_ao[B_*T_*D_MODEL];

// ---------------------------------------------------------------------------
// GEMM: Y[M,N] = X[M,K] @ W[N,K]^T      (both operands K-contiguous)
// 128x128 tile, 256 threads, 8x8 microtile, K-step 8.
// ---------------------------------------------------------------------------
#define GT  128
#define GKS 8

__global__ __launch_bounds__(256) void gemm_xwt(const float* __restrict__ X,
                                                const float* __restrict__ W,
                                                float* __restrict__ Y,
                                                int M, int N, int K) {
    __shared__ float As[GKS][GT];
    __shared__ float Bs[GKS][GT];

    const int tid = threadIdx.x;
    const int tx  = tid & 15;      // n dimension
    const int ty  = tid >> 4;      // m dimension
    const int m0  = blockIdx.y * GT;
    const int n0  = blockIdx.x * GT;

    const int lrow = tid >> 1;        // 0..127
    const int lseg = (tid & 1) * 4;   // 0 or 4

    float acc[8][8];
    #pragma unroll
    for (int i = 0; i < 8; i++)
        #pragma unroll
        for (int j = 0; j < 8; j++) acc[i][j] = 0.f;

    for (int k0 = 0; k0 < K; k0 += GKS) {
        float4 av = *(const float4*)&X[(size_t)(m0 + lrow) * K + k0 + lseg];
        float4 bv = *(const float4*)&W[(size_t)(n0 + lrow) * K + k0 + lseg];
        As[lseg + 0][lrow] = av.x; As[lseg + 1][lrow] = av.y;
        As[lseg + 2][lrow] = av.z; As[lseg + 3][lrow] = av.w;
        Bs[lseg + 0][lrow] = bv.x; Bs[lseg + 1][lrow] = bv.y;
        Bs[lseg + 2][lrow] = bv.z; Bs[lseg + 3][lrow] = bv.w;
        __syncthreads();

        #pragma unroll
        for (int kk = 0; kk < GKS; kk++) {
            float4 a0 = *(const float4*)&As[kk][ty * 8];
            float4 a1 = *(const float4*)&As[kk][ty * 8 + 4];
            float4 b0 = *(const float4*)&Bs[kk][tx * 8];
            float4 b1 = *(const float4*)&Bs[kk][tx * 8 + 4];
            float a[8] = {a0.x, a0.y, a0.z, a0.w, a1.x, a1.y, a1.z, a1.w};
            float b[8] = {b0.x, b0.y, b0.z, b0.w, b1.x, b1.y, b1.z, b1.w};
            #pragma unroll
            for (int i = 0; i < 8; i++)
                #pragma unroll
                for (int j = 0; j < 8; j++)
                    acc[i][j] += a[i] * b[j];
        }
        __syncthreads();
    }

    #pragma unroll
    for (int i = 0; i < 8; i++) {
        float4 o0 = make_float4(acc[i][0], acc[i][1], acc[i][2], acc[i][3]);
        float4 o1 = make_float4(acc[i][4], acc[i][5], acc[i][6], acc[i][7]);
        size_t base = (size_t)(m0 + ty * 8 + i) * N + n0 + tx * 8;
        *(float4*)&Y[base]     = o0;
        *(float4*)&Y[base + 4] = o1;
    }
}

// ---------------------------------------------------------------------------
// RoPE in-place on q and k.  Layout: [B,T,H,Dh], pair (d, d+64).
// ---------------------------------------------------------------------------
__global__ void rope_kernel(float* __restrict__ q, float* __restrict__ k,
                            const float* __restrict__ cosb,
                            const float* __restrict__ sinb) {
    int idx = blockIdx.x * blockDim.x + threadIdx.x;   // B*T*H*64
    int d = idx & 63;
    int h = (idx >> 6) & (N_HEADS - 1);
    int t = (idx >> 10) & (T_ - 1);
    int b = idx >> 21;
    size_t base = ((size_t)(b * T_ + t) * D_MODEL) + h * D_HEAD;

    float c0 = cosb[t * D_HEAD + d],      s0 = sinb[t * D_HEAD + d];
    float c1 = cosb[t * D_HEAD + d + 64], s1 = sinb[t * D_HEAD + d + 64];

    float q0 = q[base + d], q1 = q[base + d + 64];
    q[base + d]      = q0 * c0 - q1 * s0;
    q[base + d + 64] = q1 * c1 + q0 * s1;

    float k0 = k[base + d], k1 = k[base + d + 64];
    k[base + d]      = k0 * c0 - k1 * s0;
    k[base + d + 64] = k1 * c1 + k0 * s1;
}

// ---------------------------------------------------------------------------
// Flash attention, causal, fp32.  Per block: (qt, h, b), 64 q-rows.
// 256 threads = 16(tx: keys/cols) x 16(ty: q rows).  Thread owns 4 q-rows.
// ---------------------------------------------------------------------------
#define BQ  64
#define BK  64
#define PAD 132   // 128 + 4 floats padding to break LDS bank conflicts

__global__ __launch_bounds__(256) void attn_kernel(const float* __restrict__ Q,
                                                   const float* __restrict__ K,
                                                   const float* __restrict__ V,
                                                   float* __restrict__ O) {
    extern __shared__ float sm[];
    float* Qs = sm;                 // BQ * PAD
    float* Ks = Qs + BQ * PAD;      // BK * PAD
    float* Vs = Ks + BK * PAD;      // BK * PAD
    float* sP = Vs + BK * PAD;      // BQ * BK

    const int qt = blockIdx.x, h = blockIdx.y, b = blockIdx.z;
    const int tid = threadIdx.x;
    const int tx = tid & 15, ty = tid >> 4;

    // Load Q tile (RoPE already applied): 64 rows x 128 floats
    for (int it = tid; it < BQ * 32; it += 256) {
        int r = it >> 5, c4 = (it & 31) << 2;
        int t = qt * BQ + r;
        *(float4*)&Qs[r * PAD + c4] =
            *(const float4*)&Q[((size_t)(b * T_ + t) * D_MODEL) + h * D_HEAD + c4];
    }

    float m_i[4], l_i[4], acc[4][8];
    #pragma unroll
    for (int i = 0; i < 4; i++) {
        m_i[i] = -INFINITY; l_i[i] = 0.f;
        #pragma unroll
        for (int c = 0; c < 8; c++) acc[i][c] = 0.f;
    }

    const float scale = 0.08838834764831845f;   // 1/sqrt(128)

    for (int kt = 0; kt <= qt; kt++) {
        __syncthreads();   // protect Ks/Vs/sP from previous iteration readers
        for (int it = tid; it < BK * 32; it += 256) {
            int r = it >> 5, c4 = (it & 31) << 2;
            int t = kt * BK + r;
            size_t base = ((size_t)(b * T_ + t) * D_MODEL) + h * D_HEAD + c4;
            *(float4*)&Ks[r * PAD + c4] = *(const float4*)&K[base];
            *(float4*)&Vs[r * PAD + c4] = *(const float4*)&V[base];
        }
        __syncthreads();

        // --- scores: s[i][j] = Q[ty*4+i] . K[tx*4+j] ---
        float s[4][4];
        #pragma unroll
        for (int i = 0; i < 4; i++)
            #pragma unroll
            for (int j = 0; j < 4; j++) s[i][j] = 0.f;

        #pragma unroll 4
        for (int d4 = 0; d4 < D_HEAD; d4 += 4) {
            float4 qv[4], kv[4];
            #pragma unroll
            for (int i = 0; i < 4; i++) qv[i] = *(const float4*)&Qs[(ty * 4 + i) * PAD + d4];
            #pragma unroll
            for (int j = 0; j < 4; j++) kv[j] = *(const float4*)&Ks[(tx * 4 + j) * PAD + d4];
            #pragma unroll
            for (int i = 0; i < 4; i++)
                #pragma unroll
                for (int j = 0; j < 4; j++)
                    s[i][j] += qv[i].x * kv[j].x + qv[i].y * kv[j].y +
                               qv[i].z * kv[j].z + qv[i].w * kv[j].w;
        }

        const bool diag = (kt == qt);
        #pragma unroll
        for (int i = 0; i < 4; i++)
            #pragma unroll
            for (int j = 0; j < 4; j++) {
                if (diag && (tx * 4 + j) > (ty * 4 + i)) s[i][j] = -INFINITY;
                else                                     s[i][j] *= scale;
            }

        // --- online softmax per row (16 tx-lanes share each row) ---
        #pragma unroll
        for (int i = 0; i < 4; i++) {
            float rm = fmaxf(fmaxf(s[i][0], s[i][1]), fmaxf(s[i][2], s[i][3]));
            #pragma unroll
            for (int off = 8; off >= 1; off >>= 1)
                rm = fmaxf(rm, __shfl_xor_sync(0xffffffffu, rm, off));
            float m_new = fmaxf(m_i[i], rm);
            float alpha = __expf(m_i[i] - m_new);
            float p0 = __expf(s[i][0] - m_new);
            float p1 = __expf(s[i][1] - m_new);
            float p2 = __expf(s[i][2] - m_new);
            float p3 = __expf(s[i][3] - m_new);
            float rs = p0 + p1 + p2 + p3;
            #pragma unroll
            for (int off = 8; off >= 1; off >>= 1)
                rs += __shfl_xor_sync(0xffffffffu, rs, off);
            m_i[i] = m_new;
            l_i[i] = l_i[i] * alpha + rs;
            #pragma unroll
            for (int c = 0; c < 8; c++) acc[i][c] *= alpha;
            int rb = (ty * 4 + i) * BK + tx * 4;
            sP[rb + 0] = p0; sP[rb + 1] = p1; sP[rb + 2] = p2; sP[rb + 3] = p3;
        }
        __syncthreads();

        // --- acc += P @ V  (thread cols: tx*8 .. tx*8+7) ---
        #pragma unroll 4
        for (int k = 0; k < BK; k++) {
            float4 v0 = *(const float4*)&Vs[k * PAD + tx * 8];
            float4 v1 = *(const float4*)&Vs[k * PAD + tx * 8 + 4];
            #pragma unroll
            for (int i = 0; i < 4; i++) {
                float p = sP[(ty * 4 + i) * BK + k];
                acc[i][0] += p * v0.x; acc[i][1] += p * v0.y;
                acc[i][2] += p * v0.z; acc[i][3] += p * v0.w;
                acc[i][4] += p * v1.x; acc[i][5] += p * v1.y;
                acc[i][6] += p * v1.z; acc[i][7] += p * v1.w;
            }
        }
    }

    // --- normalize and write: layout [B,T,H*Dh] ---
    #pragma unroll
    for (int i = 0; i < 4; i++) {
        float inv = 1.f / l_i[i];
        int t = qt * BQ + ty * 4 + i;
        size_t base = ((size_t)(b * T_ + t) * D_MODEL) + h * D_HEAD + tx * 8;
        float4 o0 = make_float4(acc[i][0] * inv, acc[i][1] * inv,
                                acc[i][2] * inv, acc[i][3] * inv);
        float4 o1 = make_float4(acc[i][4] * inv, acc[i][5] * inv,
                                acc[i][6] * inv, acc[i][7] * inv);
        *(float4*)&O[base]     = o0;
        *(float4*)&O[base + 4] = o1;
    }
}

// ---------------------------------------------------------------------------
extern "C" void kernel_launch(void* const* d_in, const int* in_sizes, int n_in,
                              void* d_out, int out_size) {
    const float* x  = (const float*)d_in[0];
    const float* rc = (const float*)d_in[1];
    const float* rs = (const float*)d_in[2];
    const float* wq = (const float*)d_in[3];
    const float* wk = (const float*)d_in[4];
    const float* wv = (const float*)d_in[5];
    const float* wo = (const float*)d_in[6];
    float* out = (float*)d_out;

    float *q, *k, *v, *ao;
    cudaGetSymbolAddress((void**)&q,  g_q);
    cudaGetSymbolAddress((void**)&k,  g_k);
    cudaGetSymbolAddress((void**)&v,  g_v);
    cudaGetSymbolAddress((void**)&ao, g_ao);

    dim3 gb(D_MODEL / GT, M_TOTAL / GT);   // (16, 64)

    gemm_xwt<<<gb, 256>>>(x, wq, q, M_TOTAL, D_MODEL, D_MODEL);
    gemm_xwt<<<gb, 256>>>(x, wk, k, M_TOTAL, D_MODEL, D_MODEL);
    gemm_xwt<<<gb, 256>>>(x, wv, v, M_TOTAL, D_MODEL, D_MODEL);

    int nrope = B_ * T_ * N_HEADS * 64;
    rope_kernel<<<nrope / 256, 256>>>(q, k, rc, rs);

    size_t smem = (size_t)(3 * BQ * PAD + BQ * BK) * sizeof(float);  // ~115 KB
    cudaFuncSetAttribute(attn_kernel,
                         cudaFuncAttributeMaxDynamicSharedMemorySize, (int)smem);
    attn_kernel<<<dim3(T_ / BQ, N_HEADS, B_), 256, smem>>>(q, k, v, ao);

    gemm_xwt<<<gb, 256>>>(ao, wo, out, M_TOTAL, D_MODEL, D_MODEL);
}

// round 3
// speedup vs baseline: 1.8545x; 1.8545x over previous
#include <cuda_runtime.h>
#include <math.h>
#include <stdint.h>

#define D_MODEL 2048
#define N_HEADS 16
#define D_HEAD  128
#define B_      4
#define T_      2048
#define M_TOTAL (B_*T_)   // 8192

// Scratch: __device__ globals (no allocation allowed in kernel_launch).
__device__ float g_q [B_*T_*D_MODEL];
__device__ float g_k [B_*T_*D_MODEL];
__device__ float g_v [B_*T_*D_MODEL];
__device__ float g_ao[B_*T_*D_MODEL];
__device__ float g_xt[M_TOTAL*D_MODEL];   // tf32-rounded activations
__device__ float g_wt[D_MODEL*D_MODEL];   // tf32-rounded weight (reused)

// ---------------------------------------------------------------------------
// tf32 round-to-nearest pre-pass (elementwise, float4 vectorized)
// ---------------------------------------------------------------------------
__global__ void to_tf32(const float* __restrict__ in, float* __restrict__ out) {
    int i = (blockIdx.x * blockDim.x + threadIdx.x) * 4;
    float4 v = *(const float4*)(in + i);
    uint32_t r0, r1, r2, r3;
    asm("cvt.rna.tf32.f32 %0, %1;" : "=r"(r0) : "f"(v.x));
    asm("cvt.rna.tf32.f32 %0, %1;" : "=r"(r1) : "f"(v.y));
    asm("cvt.rna.tf32.f32 %0, %1;" : "=r"(r2) : "f"(v.z));
    asm("cvt.rna.tf32.f32 %0, %1;" : "=r"(r3) : "f"(v.w));
    float4 o = make_float4(__uint_as_float(r0), __uint_as_float(r1),
                           __uint_as_float(r2), __uint_as_float(r3));
    *(float4*)(out + i) = o;
}

// ---------------------------------------------------------------------------
// mma.sync tf32 GEMM: Y[M,N] = X[M,K] @ W[N,K]^T   (M=8192, N=K=2048)
// CTA 128x128, 8 warps (warp tile 32x64), K-chunk 16, cp.async double buffer.
// ---------------------------------------------------------------------------
#define GM 128
#define GN 128
#define CH 16          // K elements per chunk
#define SROW 20        // smem row stride in floats (16 + 4 pad, conflict-free)
#define NCHUNK (D_MODEL / CH)   // 128

#define CP_ASYNC16(dst, src) \
    asm volatile("cp.async.cg.shared.global [%0], [%1], 16;" :: "r"(dst), "l"(src) : "memory")

__device__ __forceinline__ void mma_tf32(float* d, const uint32_t* a, const uint32_t* b) {
    asm volatile(
        "mma.sync.aligned.m16n8k8.row.col.f32.tf32.tf32.f32 "
        "{%0,%1,%2,%3}, {%4,%5,%6,%7}, {%8,%9}, {%0,%1,%2,%3};"
        : "+f"(d[0]), "+f"(d[1]), "+f"(d[2]), "+f"(d[3])
        : "r"(a[0]), "r"(a[1]), "r"(a[2]), "r"(a[3]), "r"(b[0]), "r"(b[1]));
}

__global__ __launch_bounds__(256, 2) void gemm_tc(const float* __restrict__ X,
                                                  const float* __restrict__ W,
                                                  float* __restrict__ Y) {
    __shared__ float As[2][GM * SROW];
    __shared__ float Bs[2][GN * SROW];

    const int tid  = threadIdx.x;
    const int wid  = tid >> 5;
    const int lane = tid & 31;
    const int qr   = lane >> 2;     // 0..7
    const int qc   = lane & 3;      // 0..3
    const int warpM = wid & 3;      // 4 warps over 128 rows
    const int warpN = wid >> 2;     // 2 warps over 128 cols
    const int m0 = blockIdx.y * GM;
    const int n0 = blockIdx.x * GN;

    const float* Arow = X + (size_t)m0 * D_MODEL;
    const float* Brow = W + (size_t)n0 * D_MODEL;

    // prefetch helper indices: 1024 float4 per chunk (A 512 + B 512), 4/thread
    uint32_t As_base[2], Bs_base[2];
    As_base[0] = (uint32_t)__cvta_generic_to_shared(&As[0][0]);
    As_base[1] = (uint32_t)__cvta_generic_to_shared(&As[1][0]);
    Bs_base[0] = (uint32_t)__cvta_generic_to_shared(&Bs[0][0]);
    Bs_base[1] = (uint32_t)__cvta_generic_to_shared(&Bs[1][0]);

    float acc[2][8][4];
    #pragma unroll
    for (int mt = 0; mt < 2; mt++)
        #pragma unroll
        for (int nt = 0; nt < 8; nt++)
            #pragma unroll
            for (int c = 0; c < 4; c++) acc[mt][nt][c] = 0.f;

    // ---- prefetch chunk 0 ----
    #pragma unroll
    for (int u = 0; u < 4; u++) {
        int idx = tid + u * 256;          // 0..1023
        int isB = idx >> 9;               // 0: A, 1: B
        int i2  = idx & 511;
        int row = i2 >> 2;
        int seg = i2 & 3;
        const float* src = (isB ? Brow : Arow) + (size_t)row * D_MODEL + seg * 4;
        uint32_t dst = (isB ? Bs_base[0] : As_base[0]) + (row * SROW + seg * 4) * 4;
        CP_ASYNC16(dst, src);
    }
    asm volatile("cp.async.commit_group;" ::: "memory");

    for (int i = 0; i < NCHUNK; i++) {
        const int s = i & 1;
        // prefetch next chunk
        if (i + 1 < NCHUNK) {
            const int k0 = (i + 1) * CH;
            const int sn = (i + 1) & 1;
            #pragma unroll
            for (int u = 0; u < 4; u++) {
                int idx = tid + u * 256;
                int isB = idx >> 9;
                int i2  = idx & 511;
                int row = i2 >> 2;
                int seg = i2 & 3;
                const float* src = (isB ? Brow : Arow) + (size_t)row * D_MODEL + k0 + seg * 4;
                uint32_t dst = (isB ? Bs_base[sn] : As_base[sn]) + (row * SROW + seg * 4) * 4;
                CP_ASYNC16(dst, src);
            }
            asm volatile("cp.async.commit_group;" ::: "memory");
            asm volatile("cp.async.wait_group 1;" ::: "memory");
        } else {
            asm volatile("cp.async.wait_group 0;" ::: "memory");
        }
        __syncthreads();

        const float* Acur = &As[s][0];
        const float* Bcur = &Bs[s][0];

        #pragma unroll
        for (int k8 = 0; k8 < CH; k8 += 8) {
            uint32_t a[2][4], b[8][2];
            #pragma unroll
            for (int mt = 0; mt < 2; mt++) {
                int r = warpM * 32 + mt * 16 + qr;
                a[mt][0] = __float_as_uint(Acur[r * SROW + k8 + qc]);
                a[mt][1] = __float_as_uint(Acur[(r + 8) * SROW + k8 + qc]);
                a[mt][2] = __float_as_uint(Acur[r * SROW + k8 + qc + 4]);
                a[mt][3] = __float_as_uint(Acur[(r + 8) * SROW + k8 + qc + 4]);
            }
            #pragma unroll
            for (int nt = 0; nt < 8; nt++) {
                int n = warpN * 64 + nt * 8 + qr;
                b[nt][0] = __float_as_uint(Bcur[n * SROW + k8 + qc]);
                b[nt][1] = __float_as_uint(Bcur[n * SROW + k8 + qc + 4]);
            }
            #pragma unroll
            for (int mt = 0; mt < 2; mt++)
                #pragma unroll
                for (int nt = 0; nt < 8; nt++)
                    mma_tf32(acc[mt][nt], a[mt], b[nt]);
        }
        __syncthreads();
    }

    // ---- epilogue: fragment layout c0,c1 @ (qr, qc*2), c2,c3 @ (qr+8, qc*2)
    #pragma unroll
    for (int mt = 0; mt < 2; mt++) {
        #pragma unroll
        for (int nt = 0; nt < 8; nt++) {
            int r0 = m0 + warpM * 32 + mt * 16 + qr;
            int cc = n0 + warpN * 64 + nt * 8 + qc * 2;
            *(float2*)&Y[(size_t)r0 * D_MODEL + cc]       = make_float2(acc[mt][nt][0], acc[mt][nt][1]);
            *(float2*)&Y[(size_t)(r0 + 8) * D_MODEL + cc] = make_float2(acc[mt][nt][2], acc[mt][nt][3]);
        }
    }
}

// ---------------------------------------------------------------------------
// RoPE in-place on q and k.  Layout: [B,T,H,Dh], pair (d, d+64).
// ---------------------------------------------------------------------------
__global__ void rope_kernel(float* __restrict__ q, float* __restrict__ k,
                            const float* __restrict__ cosb,
                            const float* __restrict__ sinb) {
    int idx = blockIdx.x * blockDim.x + threadIdx.x;   // B*T*H*64
    int d = idx & 63;
    int h = (idx >> 6) & (N_HEADS - 1);
    int t = (idx >> 10) & (T_ - 1);
    int b = idx >> 21;
    size_t base = ((size_t)(b * T_ + t) * D_MODEL) + h * D_HEAD;

    float c0 = cosb[t * D_HEAD + d],      s0 = sinb[t * D_HEAD + d];
    float c1 = cosb[t * D_HEAD + d + 64], s1 = sinb[t * D_HEAD + d + 64];

    float q0 = q[base + d], q1 = q[base + d + 64];
    q[base + d]      = q0 * c0 - q1 * s0;
    q[base + d + 64] = q1 * c1 + q0 * s1;

    float k0 = k[base + d], k1 = k[base + d + 64];
    k[base + d]      = k0 * c0 - k1 * s0;
    k[base + d + 64] = k1 * c1 + k0 * s1;
}

// ---------------------------------------------------------------------------
// Flash attention, causal, fp32 (unchanged passing version).
// ---------------------------------------------------------------------------
#define BQ  64
#define BK  64
#define PAD 132

__global__ __launch_bounds__(256) void attn_kernel(const float* __restrict__ Q,
                                                   const float* __restrict__ K,
                                                   const float* __restrict__ V,
                                                   float* __restrict__ O) {
    extern __shared__ float smf[];
    float* Qs = smf;
    float* Ks = Qs + BQ * PAD;
    float* Vs = Ks + BK * PAD;
    float* sP = Vs + BK * PAD;

    const int qt = blockIdx.x, h = blockIdx.y, b = blockIdx.z;
    const int tid = threadIdx.x;
    const int tx = tid & 15, ty = tid >> 4;

    for (int it = tid; it < BQ * 32; it += 256) {
        int r = it >> 5, c4 = (it & 31) << 2;
        int t = qt * BQ + r;
        *(float4*)&Qs[r * PAD + c4] =
            *(const float4*)&Q[((size_t)(b * T_ + t) * D_MODEL) + h * D_HEAD + c4];
    }

    float m_i[4], l_i[4], acc[4][8];
    #pragma unroll
    for (int i = 0; i < 4; i++) {
        m_i[i] = -INFINITY; l_i[i] = 0.f;
        #pragma unroll
        for (int c = 0; c < 8; c++) acc[i][c] = 0.f;
    }

    const float scale = 0.08838834764831845f;

    for (int kt = 0; kt <= qt; kt++) {
        __syncthreads();
        for (int it = tid; it < BK * 32; it += 256) {
            int r = it >> 5, c4 = (it & 31) << 2;
            int t = kt * BK + r;
            size_t base = ((size_t)(b * T_ + t) * D_MODEL) + h * D_HEAD + c4;
            *(float4*)&Ks[r * PAD + c4] = *(const float4*)&K[base];
            *(float4*)&Vs[r * PAD + c4] = *(const float4*)&V[base];
        }
        __syncthreads();

        float s[4][4];
        #pragma unroll
        for (int i = 0; i < 4; i++)
            #pragma unroll
            for (int j = 0; j < 4; j++) s[i][j] = 0.f;

        #pragma unroll 4
        for (int d4 = 0; d4 < D_HEAD; d4 += 4) {
            float4 qv[4], kv[4];
            #pragma unroll
            for (int i = 0; i < 4; i++) qv[i] = *(const float4*)&Qs[(ty * 4 + i) * PAD + d4];
            #pragma unroll
            for (int j = 0; j < 4; j++) kv[j] = *(const float4*)&Ks[(tx * 4 + j) * PAD + d4];
            #pragma unroll
            for (int i = 0; i < 4; i++)
                #pragma unroll
                for (int j = 0; j < 4; j++)
                    s[i][j] += qv[i].x * kv[j].x + qv[i].y * kv[j].y +
                               qv[i].z * kv[j].z + qv[i].w * kv[j].w;
        }

        const bool diag = (kt == qt);
        #pragma unroll
        for (int i = 0; i < 4; i++)
            #pragma unroll
            for (int j = 0; j < 4; j++) {
                if (diag && (tx * 4 + j) > (ty * 4 + i)) s[i][j] = -INFINITY;
                else                                     s[i][j] *= scale;
            }

        #pragma unroll
        for (int i = 0; i < 4; i++) {
            float rm = fmaxf(fmaxf(s[i][0], s[i][1]), fmaxf(s[i][2], s[i][3]));
            #pragma unroll
            for (int off = 8; off >= 1; off >>= 1)
                rm = fmaxf(rm, __shfl_xor_sync(0xffffffffu, rm, off));
            float m_new = fmaxf(m_i[i], rm);
            float alpha = __expf(m_i[i] - m_new);
            float p0 = __expf(s[i][0] - m_new);
            float p1 = __expf(s[i][1] - m_new);
            float p2 = __expf(s[i][2] - m_new);
            float p3 = __expf(s[i][3] - m_new);
            float rs = p0 + p1 + p2 + p3;
            #pragma unroll
            for (int off = 8; off >= 1; off >>= 1)
                rs += __shfl_xor_sync(0xffffffffu, rs, off);
            m_i[i] = m_new;
            l_i[i] = l_i[i] * alpha + rs;
            #pragma unroll
            for (int c = 0; c < 8; c++) acc[i][c] *= alpha;
            int rb = (ty * 4 + i) * BK + tx * 4;
            sP[rb + 0] = p0; sP[rb + 1] = p1; sP[rb + 2] = p2; sP[rb + 3] = p3;
        }
        __syncthreads();

        #pragma unroll 4
        for (int k = 0; k < BK; k++) {
            float4 v0 = *(const float4*)&Vs[k * PAD + tx * 8];
            float4 v1 = *(const float4*)&Vs[k * PAD + tx * 8 + 4];
            #pragma unroll
            for (int i = 0; i < 4; i++) {
                float p = sP[(ty * 4 + i) * BK + k];
                acc[i][0] += p * v0.x; acc[i][1] += p * v0.y;
                acc[i][2] += p * v0.z; acc[i][3] += p * v0.w;
                acc[i][4] += p * v1.x; acc[i][5] += p * v1.y;
                acc[i][6] += p * v1.z; acc[i][7] += p * v1.w;
            }
        }
    }

    #pragma unroll
    for (int i = 0; i < 4; i++) {
        float inv = 1.f / l_i[i];
        int t = qt * BQ + ty * 4 + i;
        size_t base = ((size_t)(b * T_ + t) * D_MODEL) + h * D_HEAD + tx * 8;
        float4 o0 = make_float4(acc[i][0] * inv, acc[i][1] * inv,
                                acc[i][2] * inv, acc[i][3] * inv);
        float4 o1 = make_float4(acc[i][4] * inv, acc[i][5] * inv,
                                acc[i][6] * inv, acc[i][7] * inv);
        *(float4*)&O[base]     = o0;
        *(float4*)&O[base + 4] = o1;
    }
}

// ---------------------------------------------------------------------------
extern "C" void kernel_launch(void* const* d_in, const int* in_sizes, int n_in,
                              void* d_out, int out_size) {
    const float* x  = (const float*)d_in[0];
    const float* rc = (const float*)d_in[1];
    const float* rs = (const float*)d_in[2];
    const float* wq = (const float*)d_in[3];
    const float* wk = (const float*)d_in[4];
    const float* wv = (const float*)d_in[5];
    const float* wo = (const float*)d_in[6];
    float* out = (float*)d_out;

    float *q, *k, *v, *ao, *xt, *wt;
    cudaGetSymbolAddress((void**)&q,  g_q);
    cudaGetSymbolAddress((void**)&k,  g_k);
    cudaGetSymbolAddress((void**)&v,  g_v);
    cudaGetSymbolAddress((void**)&ao, g_ao);
    cudaGetSymbolAddress((void**)&xt, g_xt);
    cudaGetSymbolAddress((void**)&wt, g_wt);

    const int NX = M_TOTAL * D_MODEL;   // 16.7M
    const int NW = D_MODEL * D_MODEL;   // 4.2M
    dim3 gb(D_MODEL / GN, M_TOTAL / GM);   // (16, 64)

    to_tf32<<<NX / 1024, 256>>>(x, xt);
    to_tf32<<<NW / 1024, 256>>>(wq, wt);
    gemm_tc<<<gb, 256>>>(xt, wt, q);
    to_tf32<<<NW / 1024, 256>>>(wk, wt);
    gemm_tc<<<gb, 256>>>(xt, wt, k);
    to_tf32<<<NW / 1024, 256>>>(wv, wt);
    gemm_tc<<<gb, 256>>>(xt, wt, v);

    int nrope = B_ * T_ * N_HEADS * 64;
    rope_kernel<<<nrope / 256, 256>>>(q, k, rc, rs);

    size_t smem = (size_t)(3 * BQ * PAD + BQ * BK) * sizeof(float);
    cudaFuncSetAttribute(attn_kernel,
                         cudaFuncAttributeMaxDynamicSharedMemorySize, (int)smem);
    attn_kernel<<<dim3(T_ / BQ, N_HEADS, B_), 256, smem>>>(q, k, v, ao);

    to_tf32<<<NX / 1024, 256>>>(ao, xt);
    to_tf32<<<NW / 1024, 256>>>(wo, wt);
    gemm_tc<<<gb, 256>>>(xt, wt, out);
}

// round 4
// speedup vs baseline: 3.8549x; 2.0786x over previous
#include <cuda_runtime.h>
#include <math.h>
#include <stdint.h>

#define D_MODEL 2048
#define N_HEADS 16
#define D_HEAD  128
#define B_      4
#define T_      2048
#define M_TOTAL (B_*T_)   // 8192

// Scratch: __device__ globals (no allocation allowed in kernel_launch).
__device__ float g_q [B_*T_*D_MODEL];
__device__ float g_k [B_*T_*D_MODEL];
__device__ float g_v [B_*T_*D_MODEL];
__device__ float g_ao[B_*T_*D_MODEL];
__device__ float g_xt[M_TOTAL*D_MODEL];   // tf32-rounded activations
__device__ float g_wt[D_MODEL*D_MODEL];   // tf32-rounded weight (reused)

__device__ __forceinline__ float tf32r(float x) {
    uint32_t r;
    asm("cvt.rna.tf32.f32 %0, %1;" : "=r"(r) : "f"(x));
    return __uint_as_float(r);
}

// ---------------------------------------------------------------------------
// tf32 round-to-nearest pre-pass (elementwise, float4 vectorized)
// ---------------------------------------------------------------------------
__global__ void to_tf32(const float* __restrict__ in, float* __restrict__ out) {
    int i = (blockIdx.x * blockDim.x + threadIdx.x) * 4;
    float4 v = *(const float4*)(in + i);
    float4 o = make_float4(tf32r(v.x), tf32r(v.y), tf32r(v.z), tf32r(v.w));
    *(float4*)(out + i) = o;
}

// ---------------------------------------------------------------------------
// mma.sync tf32 GEMM: Y[M,N] = X[M,K] @ W[N,K]^T   (unchanged, passing)
// ---------------------------------------------------------------------------
#define GM 128
#define GN 128
#define CH 16
#define SROW 20
#define NCHUNK (D_MODEL / CH)

#define CP_ASYNC16(dst, src) \
    asm volatile("cp.async.cg.shared.global [%0], [%1], 16;" :: "r"(dst), "l"(src) : "memory")

__device__ __forceinline__ void mma_tf32(float* d, const uint32_t* a, const uint32_t* b) {
    asm volatile(
        "mma.sync.aligned.m16n8k8.row.col.f32.tf32.tf32.f32 "
        "{%0,%1,%2,%3}, {%4,%5,%6,%7}, {%8,%9}, {%0,%1,%2,%3};"
        : "+f"(d[0]), "+f"(d[1]), "+f"(d[2]), "+f"(d[3])
        : "r"(a[0]), "r"(a[1]), "r"(a[2]), "r"(a[3]), "r"(b[0]), "r"(b[1]));
}

__global__ __launch_bounds__(256, 2) void gemm_tc(const float* __restrict__ X,
                                                  const float* __restrict__ W,
                                                  float* __restrict__ Y) {
    __shared__ float As[2][GM * SROW];
    __shared__ float Bs[2][GN * SROW];

    const int tid  = threadIdx.x;
    const int wid  = tid >> 5;
    const int lane = tid & 31;
    const int qr   = lane >> 2;
    const int qc   = lane & 3;
    const int warpM = wid & 3;
    const int warpN = wid >> 2;
    const int m0 = blockIdx.y * GM;
    const int n0 = blockIdx.x * GN;

    const float* Arow = X + (size_t)m0 * D_MODEL;
    const float* Brow = W + (size_t)n0 * D_MODEL;

    uint32_t As_base[2], Bs_base[2];
    As_base[0] = (uint32_t)__cvta_generic_to_shared(&As[0][0]);
    As_base[1] = (uint32_t)__cvta_generic_to_shared(&As[1][0]);
    Bs_base[0] = (uint32_t)__cvta_generic_to_shared(&Bs[0][0]);
    Bs_base[1] = (uint32_t)__cvta_generic_to_shared(&Bs[1][0]);

    float acc[2][8][4];
    #pragma unroll
    for (int mt = 0; mt < 2; mt++)
        #pragma unroll
        for (int nt = 0; nt < 8; nt++)
            #pragma unroll
            for (int c = 0; c < 4; c++) acc[mt][nt][c] = 0.f;

    #pragma unroll
    for (int u = 0; u < 4; u++) {
        int idx = tid + u * 256;
        int isB = idx >> 9;
        int i2  = idx & 511;
        int row = i2 >> 2;
        int seg = i2 & 3;
        const float* src = (isB ? Brow : Arow) + (size_t)row * D_MODEL + seg * 4;
        uint32_t dst = (isB ? Bs_base[0] : As_base[0]) + (row * SROW + seg * 4) * 4;
        CP_ASYNC16(dst, src);
    }
    asm volatile("cp.async.commit_group;" ::: "memory");

    for (int i = 0; i < NCHUNK; i++) {
        const int s = i & 1;
        if (i + 1 < NCHUNK) {
            const int k0 = (i + 1) * CH;
            const int sn = (i + 1) & 1;
            #pragma unroll
            for (int u = 0; u < 4; u++) {
                int idx = tid + u * 256;
                int isB = idx >> 9;
                int i2  = idx & 511;
                int row = i2 >> 2;
                int seg = i2 & 3;
                const float* src = (isB ? Brow : Arow) + (size_t)row * D_MODEL + k0 + seg * 4;
                uint32_t dst = (isB ? Bs_base[sn] : As_base[sn]) + (row * SROW + seg * 4) * 4;
                CP_ASYNC16(dst, src);
            }
            asm volatile("cp.async.commit_group;" ::: "memory");
            asm volatile("cp.async.wait_group 1;" ::: "memory");
        } else {
            asm volatile("cp.async.wait_group 0;" ::: "memory");
        }
        __syncthreads();

        const float* Acur = &As[s][0];
        const float* Bcur = &Bs[s][0];

        #pragma unroll
        for (int k8 = 0; k8 < CH; k8 += 8) {
            uint32_t a[2][4], b[8][2];
            #pragma unroll
            for (int mt = 0; mt < 2; mt++) {
                int r = warpM * 32 + mt * 16 + qr;
                a[mt][0] = __float_as_uint(Acur[r * SROW + k8 + qc]);
                a[mt][1] = __float_as_uint(Acur[(r + 8) * SROW + k8 + qc]);
                a[mt][2] = __float_as_uint(Acur[r * SROW + k8 + qc + 4]);
                a[mt][3] = __float_as_uint(Acur[(r + 8) * SROW + k8 + qc + 4]);
            }
            #pragma unroll
            for (int nt = 0; nt < 8; nt++) {
                int n = warpN * 64 + nt * 8 + qr;
                b[nt][0] = __float_as_uint(Bcur[n * SROW + k8 + qc]);
                b[nt][1] = __float_as_uint(Bcur[n * SROW + k8 + qc + 4]);
            }
            #pragma unroll
            for (int mt = 0; mt < 2; mt++)
                #pragma unroll
                for (int nt = 0; nt < 8; nt++)
                    mma_tf32(acc[mt][nt], a[mt], b[nt]);
        }
        __syncthreads();
    }

    #pragma unroll
    for (int mt = 0; mt < 2; mt++) {
        #pragma unroll
        for (int nt = 0; nt < 8; nt++) {
            int r0 = m0 + warpM * 32 + mt * 16 + qr;
            int cc = n0 + warpN * 64 + nt * 8 + qc * 2;
            *(float2*)&Y[(size_t)r0 * D_MODEL + cc]       = make_float2(acc[mt][nt][0], acc[mt][nt][1]);
            *(float2*)&Y[(size_t)(r0 + 8) * D_MODEL + cc] = make_float2(acc[mt][nt][2], acc[mt][nt][3]);
        }
    }
}

// ---------------------------------------------------------------------------
// RoPE in-place on q and k, writing tf32-rounded results.
// ---------------------------------------------------------------------------
__global__ void rope_kernel(float* __restrict__ q, float* __restrict__ k,
                            const float* __restrict__ cosb,
                            const float* __restrict__ sinb) {
    int idx = blockIdx.x * blockDim.x + threadIdx.x;
    int d = idx & 63;
    int h = (idx >> 6) & (N_HEADS - 1);
    int t = (idx >> 10) & (T_ - 1);
    int b = idx >> 21;
    size_t base = ((size_t)(b * T_ + t) * D_MODEL) + h * D_HEAD;

    float c0 = cosb[t * D_HEAD + d],      s0 = sinb[t * D_HEAD + d];
    float c1 = cosb[t * D_HEAD + d + 64], s1 = sinb[t * D_HEAD + d + 64];

    float q0 = q[base + d], q1 = q[base + d + 64];
    q[base + d]      = tf32r(q0 * c0 - q1 * s0);
    q[base + d + 64] = tf32r(q1 * c1 + q0 * s1);

    float k0 = k[base + d], k1 = k[base + d + 64];
    k[base + d]      = tf32r(k0 * c0 - k1 * s0);
    k[base + d + 64] = tf32r(k1 * c1 + k0 * s1);
}

// ---------------------------------------------------------------------------
// Tensorized flash attention (causal, tf32 mma.sync).
// Block: (qt, h, b); 128 threads = 4 warps; warp w owns q-rows [w*16, w*16+16).
// Q,K,V in gmem already tf32-rounded. Output written tf32-rounded.
// ---------------------------------------------------------------------------
#define BQ   64
#define BK   64
#define KPAD 132   // [row][d] stride for Ks/Vs
#define PPAD 68    // [qrow][key] stride for Ps

#define ATTN_SMEM ((2 * BK * KPAD + BQ * PPAD) * 4)   // 84992 bytes

__global__ __launch_bounds__(128) void attn_tc(const float* __restrict__ Q,
                                               const float* __restrict__ K,
                                               const float* __restrict__ V,
                                               float* __restrict__ O) {
    extern __shared__ float smf[];
    float* Ks = smf;                  // BK x KPAD
    float* Vs = Ks + BK * KPAD;       // BK x KPAD
    float* Ps = Vs + BK * KPAD;       // BQ x PPAD

    const int qt = blockIdx.x, h = blockIdx.y, b = blockIdx.z;
    const int tid  = threadIdx.x;
    const int w    = tid >> 5;
    const int lane = tid & 31;
    const int qr   = lane >> 2;   // 0..7
    const int qc   = lane & 3;    // 0..3

    const int rowL0 = w * 16 + qr;       // local q row (block-relative)
    const int rowL1 = rowL0 + 8;
    const size_t qg0 = (size_t)(b * T_ + qt * BQ + rowL0) * D_MODEL + h * D_HEAD;
    const size_t qg1 = qg0 + 8 * (size_t)D_MODEL;

    // ---- Q as A-fragments in registers (16 k-steps x 4 regs) ----
    uint32_t qf[16][4];
    #pragma unroll
    for (int k8 = 0; k8 < 16; k8++) {
        qf[k8][0] = __float_as_uint(__ldg(&Q[qg0 + k8 * 8 + qc]));
        qf[k8][1] = __float_as_uint(__ldg(&Q[qg1 + k8 * 8 + qc]));
        qf[k8][2] = __float_as_uint(__ldg(&Q[qg0 + k8 * 8 + qc + 4]));
        qf[k8][3] = __float_as_uint(__ldg(&Q[qg1 + k8 * 8 + qc + 4]));
    }

    float out[16][4];
    #pragma unroll
    for (int nt = 0; nt < 16; nt++)
        #pragma unroll
        for (int c = 0; c < 4; c++) out[nt][c] = 0.f;

    float m0 = -INFINITY, m1 = -INFINITY, l0 = 0.f, l1 = 0.f;
    const float scale = 0.08838834764831845f;   // 1/sqrt(128)

    for (int kt = 0; kt <= qt; kt++) {
        __syncthreads();
        // ---- load K,V tiles (64 x 128 each) ----
        for (int it = tid; it < BK * 32; it += 128) {
            int r = it >> 5, c4 = (it & 31) << 2;
            size_t base = ((size_t)(b * T_ + kt * BK + r)) * D_MODEL + h * D_HEAD + c4;
            *(float4*)&Ks[r * KPAD + c4] = *(const float4*)&K[base];
            *(float4*)&Vs[r * KPAD + c4] = *(const float4*)&V[base];
        }
        __syncthreads();

        // ---- scores: S = Q @ K^T  (8 n-tiles of 8 keys) ----
        float s[8][4];
        #pragma unroll
        for (int nt = 0; nt < 8; nt++)
            #pragma unroll
            for (int c = 0; c < 4; c++) s[nt][c] = 0.f;

        #pragma unroll
        for (int k8 = 0; k8 < 16; k8++) {
            uint32_t bfrag[8][2];
            #pragma unroll
            for (int nt = 0; nt < 8; nt++) {
                bfrag[nt][0] = __float_as_uint(Ks[(nt * 8 + qr) * KPAD + k8 * 8 + qc]);
                bfrag[nt][1] = __float_as_uint(Ks[(nt * 8 + qr) * KPAD + k8 * 8 + qc + 4]);
            }
            #pragma unroll
            for (int nt = 0; nt < 8; nt++)
                mma_tf32(s[nt], qf[k8], bfrag[nt]);
        }

        // ---- scale + causal mask ----
        const bool diag = (kt == qt);
        #pragma unroll
        for (int nt = 0; nt < 8; nt++) {
            int c0 = nt * 8 + 2 * qc, c1 = c0 + 1;
            if (diag) {
                s[nt][0] = (c0 > rowL0) ? -INFINITY : s[nt][0] * scale;
                s[nt][1] = (c1 > rowL0) ? -INFINITY : s[nt][1] * scale;
                s[nt][2] = (c0 > rowL1) ? -INFINITY : s[nt][2] * scale;
                s[nt][3] = (c1 > rowL1) ? -INFINITY : s[nt][3] * scale;
            } else {
                s[nt][0] *= scale; s[nt][1] *= scale;
                s[nt][2] *= scale; s[nt][3] *= scale;
            }
        }

        // ---- online softmax (rows qr and qr+8; quad = lanes sharing qr) ----
        float rmax0 = -INFINITY, rmax1 = -INFINITY;
        #pragma unroll
        for (int nt = 0; nt < 8; nt++) {
            rmax0 = fmaxf(rmax0, fmaxf(s[nt][0], s[nt][1]));
            rmax1 = fmaxf(rmax1, fmaxf(s[nt][2], s[nt][3]));
        }
        rmax0 = fmaxf(rmax0, __shfl_xor_sync(0xffffffffu, rmax0, 1));
        rmax0 = fmaxf(rmax0, __shfl_xor_sync(0xffffffffu, rmax0, 2));
        rmax1 = fmaxf(rmax1, __shfl_xor_sync(0xffffffffu, rmax1, 1));
        rmax1 = fmaxf(rmax1, __shfl_xor_sync(0xffffffffu, rmax1, 2));

        float mn0 = fmaxf(m0, rmax0), mn1 = fmaxf(m1, rmax1);
        float a0 = __expf(m0 - mn0),  a1 = __expf(m1 - mn1);

        float sum0 = 0.f, sum1 = 0.f;
        #pragma unroll
        for (int nt = 0; nt < 8; nt++) {
            float p0 = __expf(s[nt][0] - mn0);
            float p1 = __expf(s[nt][1] - mn0);
            float p2 = __expf(s[nt][2] - mn1);
            float p3 = __expf(s[nt][3] - mn1);
            sum0 += p0 + p1; sum1 += p2 + p3;
            *(float2*)&Ps[rowL0 * PPAD + nt * 8 + 2 * qc] = make_float2(p0, p1);
            *(float2*)&Ps[rowL1 * PPAD + nt * 8 + 2 * qc] = make_float2(p2, p3);
        }
        sum0 += __shfl_xor_sync(0xffffffffu, sum0, 1);
        sum0 += __shfl_xor_sync(0xffffffffu, sum0, 2);
        sum1 += __shfl_xor_sync(0xffffffffu, sum1, 1);
        sum1 += __shfl_xor_sync(0xffffffffu, sum1, 2);

        l0 = l0 * a0 + sum0;
        l1 = l1 * a1 + sum1;
        m0 = mn0; m1 = mn1;

        #pragma unroll
        for (int nt = 0; nt < 16; nt++) {
            out[nt][0] *= a0; out[nt][1] *= a0;
            out[nt][2] *= a1; out[nt][3] *= a1;
        }
        __syncwarp();

        // ---- out += P @ V  (P warp-private in smem) ----
        #pragma unroll
        for (int k8 = 0; k8 < 8; k8++) {
            uint32_t af[4];
            af[0] = __float_as_uint(Ps[rowL0 * PPAD + k8 * 8 + qc]);
            af[1] = __float_as_uint(Ps[rowL1 * PPAD + k8 * 8 + qc]);
            af[2] = __float_as_uint(Ps[rowL0 * PPAD + k8 * 8 + qc + 4]);
            af[3] = __float_as_uint(Ps[rowL1 * PPAD + k8 * 8 + qc + 4]);
            #pragma unroll
            for (int nt = 0; nt < 16; nt++) {
                uint32_t bf[2];
                bf[0] = __float_as_uint(Vs[(k8 * 8 + qc) * KPAD + nt * 8 + qr]);
                bf[1] = __float_as_uint(Vs[(k8 * 8 + qc + 4) * KPAD + nt * 8 + qr]);
                mma_tf32(out[nt], af, bf);
            }
        }
        __syncwarp();
    }

    // ---- normalize + store (tf32-rounded for the final GEMM) ----
    float inv0 = 1.f / l0, inv1 = 1.f / l1;
    #pragma unroll
    for (int nt = 0; nt < 16; nt++) {
        int cc = nt * 8 + 2 * qc;
        *(float2*)&O[qg0 + cc] = make_float2(tf32r(out[nt][0] * inv0),
                                             tf32r(out[nt][1] * inv0));
        *(float2*)&O[qg1 + cc] = make_float2(tf32r(out[nt][2] * inv1),
                                             tf32r(out[nt][3] * inv1));
    }
}

// ---------------------------------------------------------------------------
extern "C" void kernel_launch(void* const* d_in, const int* in_sizes, int n_in,
                              void* d_out, int out_size) {
    const float* x  = (const float*)d_in[0];
    const float* rc = (const float*)d_in[1];
    const float* rs = (const float*)d_in[2];
    const float* wq = (const float*)d_in[3];
    const float* wk = (const float*)d_in[4];
    const float* wv = (const float*)d_in[5];
    const float* wo = (const float*)d_in[6];
    float* out = (float*)d_out;

    float *q, *k, *v, *ao, *xt, *wt;
    cudaGetSymbolAddress((void**)&q,  g_q);
    cudaGetSymbolAddress((void**)&k,  g_k);
    cudaGetSymbolAddress((void**)&v,  g_v);
    cudaGetSymbolAddress((void**)&ao, g_ao);
    cudaGetSymbolAddress((void**)&xt, g_xt);
    cudaGetSymbolAddress((void**)&wt, g_wt);

    const int NX = M_TOTAL * D_MODEL;
    const int NW = D_MODEL * D_MODEL;
    dim3 gb(D_MODEL / GN, M_TOTAL / GM);

    to_tf32<<<NX / 1024, 256>>>(x, xt);
    to_tf32<<<NW / 1024, 256>>>(wq, wt);
    gemm_tc<<<gb, 256>>>(xt, wt, q);
    to_tf32<<<NW / 1024, 256>>>(wk, wt);
    gemm_tc<<<gb, 256>>>(xt, wt, k);
    to_tf32<<<NW / 1024, 256>>>(wv, wt);
    gemm_tc<<<gb, 256>>>(xt, wt, v);

    int nrope = B_ * T_ * N_HEADS * 64;
    rope_kernel<<<nrope / 256, 256>>>(q, k, rc, rs);   // writes tf32-rounded q,k
    to_tf32<<<NX / 1024, 256>>>(v, v);                 // round v in place

    cudaFuncSetAttribute(attn_tc, cudaFuncAttributeMaxDynamicSharedMemorySize,
                         ATTN_SMEM);
    attn_tc<<<dim3(T_ / BQ, N_HEADS, B_), 128, ATTN_SMEM>>>(q, k, v, ao);

    to_tf32<<<NW / 1024, 256>>>(wo, wt);
    gemm_tc<<<gb, 256>>>(ao, wt, out);
}

// round 5
// speedup vs baseline: 4.3784x; 1.1358x over previous
#include <cuda_runtime.h>
#include <math.h>
#include <stdint.h>

#define D_MODEL 2048
#define N_HEADS 16
#define D_HEAD  128
#define B_      4
#define T_      2048
#define M_TOTAL (B_*T_)   // 8192

// Scratch: __device__ globals (no allocation allowed in kernel_launch).
__device__ float g_q [B_*T_*D_MODEL];
__device__ float g_k [B_*T_*D_MODEL];
__device__ float g_v [B_*T_*D_MODEL];
__device__ float g_ao[B_*T_*D_MODEL];
__device__ float g_xt[M_TOTAL*D_MODEL];     // tf32-rounded activations
__device__ float g_wt[3*D_MODEL*D_MODEL];   // tf32-rounded weights (qkv concat / wo)

__device__ __forceinline__ float tf32r(float x) {
    uint32_t r;
    asm("cvt.rna.tf32.f32 %0, %1;" : "=r"(r) : "f"(x));
    return __uint_as_float(r);
}

__global__ void to_tf32(const float* __restrict__ in, float* __restrict__ out) {
    int i = (blockIdx.x * blockDim.x + threadIdx.x) * 4;
    float4 v = *(const float4*)(in + i);
    float4 o = make_float4(tf32r(v.x), tf32r(v.y), tf32r(v.z), tf32r(v.w));
    *(float4*)(out + i) = o;
}

#define CP_ASYNC16(dst, src) \
    asm volatile("cp.async.cg.shared.global [%0], [%1], 16;" :: "r"(dst), "l"(src) : "memory")

__device__ __forceinline__ void mma_tf32(float* d, const uint32_t* a, const uint32_t* b) {
    asm volatile(
        "mma.sync.aligned.m16n8k8.row.col.f32.tf32.tf32.f32 "
        "{%0,%1,%2,%3}, {%4,%5,%6,%7}, {%8,%9}, {%0,%1,%2,%3};"
        : "+f"(d[0]), "+f"(d[1]), "+f"(d[2]), "+f"(d[3])
        : "r"(a[0]), "r"(a[1]), "r"(a[2]), "r"(a[3]), "r"(b[0]), "r"(b[1]));
}

// ---------------------------------------------------------------------------
// GEMM v2: Y[M,N] = X[M,K] @ W[N,K]^T, CTA 128x128, CH=32, 3-stage cp.async.
// W has Nglob rows (2048 or 6144); output routed to Yq/Yk/Yv by n block.
// ---------------------------------------------------------------------------
#define CH2   32
#define SROW2 36
#define NST   3
#define STAGE_FLOATS (256 * SROW2)          // A(128 rows) + B(128 rows)
#define STAGE_BYTES  (STAGE_FLOATS * 4)     // 36864
#define BOFF_BYTES   (128 * SROW2 * 4)      // 18432
#define GEMM_SMEM    (NST * STAGE_BYTES)    // 110592
#define NCH2 (D_MODEL / CH2)                // 64

template<int ROUND>
__global__ __launch_bounds__(256, 2) void gemm3(const float* __restrict__ X,
                                                const float* __restrict__ W,
                                                float* __restrict__ Yq,
                                                float* __restrict__ Yk,
                                                float* __restrict__ Yv) {
    extern __shared__ float smd[];
    const uint32_t smem_base = (uint32_t)__cvta_generic_to_shared(smd);

    const int tid  = threadIdx.x;
    const int wid  = tid >> 5;
    const int lane = tid & 31;
    const int qr   = lane >> 2;
    const int qc   = lane & 3;
    const int warpM = wid & 3;
    const int warpN = wid >> 2;

    const int m0      = blockIdx.y * 128;
    const int n_glob  = blockIdx.x * 128;
    const int which   = n_glob >> 11;            // 0,1,2
    const int n0      = n_glob & 2047;
    float* Y = (which == 0) ? Yq : (which == 1) ? Yk : Yv;

    const float* Arow = X + (size_t)m0 * D_MODEL;
    const float* Brow = W + (size_t)n_glob * D_MODEL;

    float acc[2][8][4];
    #pragma unroll
    for (int mt = 0; mt < 2; mt++)
        #pragma unroll
        for (int nt = 0; nt < 8; nt++)
            #pragma unroll
            for (int c = 0; c < 4; c++) acc[mt][nt][c] = 0.f;

    // prefetch helper: chunk -> stage (2048 float4, 8 per thread)
    auto prefetch = [&](int chunk, int stage) {
        const int k0 = chunk * CH2;
        const uint32_t sbase = smem_base + stage * STAGE_BYTES;
        #pragma unroll
        for (int u = 0; u < 8; u++) {
            int idx = tid + u * 256;
            int isB = idx >> 10;
            int i2  = idx & 1023;
            int row = i2 >> 3;
            int seg = i2 & 7;
            const float* src = (isB ? Brow : Arow) + (size_t)row * D_MODEL + k0 + seg * 4;
            uint32_t dst = sbase + (isB ? BOFF_BYTES : 0) + (row * SROW2 + seg * 4) * 4;
            CP_ASYNC16(dst, src);
        }
    };

    prefetch(0, 0);
    asm volatile("cp.async.commit_group;" ::: "memory");
    prefetch(1, 1);
    asm volatile("cp.async.commit_group;" ::: "memory");

    int stage = 0;
    for (int i = 0; i < NCH2; i++) {
        asm volatile("cp.async.wait_group 1;" ::: "memory");
        __syncthreads();

        // prefetch chunk i+2 into the stage freed at end of iteration i-1
        if (i + 2 < NCH2) prefetch(i + 2, (stage + 2) % NST);
        asm volatile("cp.async.commit_group;" ::: "memory");

        const float* Acur = smd + stage * STAGE_FLOATS;
        const float* Bcur = Acur + 128 * SROW2;

        #pragma unroll
        for (int k8 = 0; k8 < CH2; k8 += 8) {
            uint32_t a[2][4], b[8][2];
            #pragma unroll
            for (int mt = 0; mt < 2; mt++) {
                int r = warpM * 32 + mt * 16 + qr;
                a[mt][0] = __float_as_uint(Acur[r * SROW2 + k8 + qc]);
                a[mt][1] = __float_as_uint(Acur[(r + 8) * SROW2 + k8 + qc]);
                a[mt][2] = __float_as_uint(Acur[r * SROW2 + k8 + qc + 4]);
                a[mt][3] = __float_as_uint(Acur[(r + 8) * SROW2 + k8 + qc + 4]);
            }
            #pragma unroll
            for (int nt = 0; nt < 8; nt++) {
                int n = warpN * 64 + nt * 8 + qr;
                b[nt][0] = __float_as_uint(Bcur[n * SROW2 + k8 + qc]);
                b[nt][1] = __float_as_uint(Bcur[n * SROW2 + k8 + qc + 4]);
            }
            #pragma unroll
            for (int mt = 0; mt < 2; mt++)
                #pragma unroll
                for (int nt = 0; nt < 8; nt++)
                    mma_tf32(acc[mt][nt], a[mt], b[nt]);
        }
        stage = (stage + 1) % NST;
        __syncthreads();   // all warps done with this stage before it is refilled
    }

    #pragma unroll
    for (int mt = 0; mt < 2; mt++) {
        #pragma unroll
        for (int nt = 0; nt < 8; nt++) {
            int r0 = m0 + warpM * 32 + mt * 16 + qr;
            int cc = n0 + warpN * 64 + nt * 8 + qc * 2;
            float o0 = acc[mt][nt][0], o1 = acc[mt][nt][1];
            float o2 = acc[mt][nt][2], o3 = acc[mt][nt][3];
            if (ROUND) { o0 = tf32r(o0); o1 = tf32r(o1); o2 = tf32r(o2); o3 = tf32r(o3); }
            *(float2*)&Y[(size_t)r0 * D_MODEL + cc]       = make_float2(o0, o1);
            *(float2*)&Y[(size_t)(r0 + 8) * D_MODEL + cc] = make_float2(o2, o3);
        }
    }
}

// ---------------------------------------------------------------------------
// RoPE in-place on q and k, writing tf32-rounded results.
// ---------------------------------------------------------------------------
__global__ void rope_kernel(float* __restrict__ q, float* __restrict__ k,
                            const float* __restrict__ cosb,
                            const float* __restrict__ sinb) {
    int idx = blockIdx.x * blockDim.x + threadIdx.x;
    int d = idx & 63;
    int h = (idx >> 6) & (N_HEADS - 1);
    int t = (idx >> 10) & (T_ - 1);
    int b = idx >> 21;
    size_t base = ((size_t)(b * T_ + t) * D_MODEL) + h * D_HEAD;

    float c0 = cosb[t * D_HEAD + d],      s0 = sinb[t * D_HEAD + d];
    float c1 = cosb[t * D_HEAD + d + 64], s1 = sinb[t * D_HEAD + d + 64];

    float q0 = q[base + d], q1 = q[base + d + 64];
    q[base + d]      = tf32r(q0 * c0 - q1 * s0);
    q[base + d + 64] = tf32r(q1 * c1 + q0 * s1);

    float k0 = k[base + d], k1 = k[base + d + 64];
    k[base + d]      = tf32r(k0 * c0 - k1 * s0);
    k[base + d + 64] = tf32r(k1 * c1 + k0 * s1);
}

// ---------------------------------------------------------------------------
// Tensorized flash attention (causal, tf32 mma.sync) — unchanged, passing.
// ---------------------------------------------------------------------------
#define BQ   64
#define BK   64
#define KPAD 132
#define PPAD 68
#define ATTN_SMEM ((2 * BK * KPAD + BQ * PPAD) * 4)

__global__ __launch_bounds__(128) void attn_tc(const float* __restrict__ Q,
                                               const float* __restrict__ K,
                                               const float* __restrict__ V,
                                               float* __restrict__ O) {
    extern __shared__ float smf[];
    float* Ks = smf;
    float* Vs = Ks + BK * KPAD;
    float* Ps = Vs + BK * KPAD;

    const int qt = blockIdx.x, h = blockIdx.y, b = blockIdx.z;
    const int tid  = threadIdx.x;
    const int w    = tid >> 5;
    const int lane = tid & 31;
    const int qr   = lane >> 2;
    const int qc   = lane & 3;

    const int rowL0 = w * 16 + qr;
    const int rowL1 = rowL0 + 8;
    const size_t qg0 = (size_t)(b * T_ + qt * BQ + rowL0) * D_MODEL + h * D_HEAD;
    const size_t qg1 = qg0 + 8 * (size_t)D_MODEL;

    uint32_t qf[16][4];
    #pragma unroll
    for (int k8 = 0; k8 < 16; k8++) {
        qf[k8][0] = __float_as_uint(__ldg(&Q[qg0 + k8 * 8 + qc]));
        qf[k8][1] = __float_as_uint(__ldg(&Q[qg1 + k8 * 8 + qc]));
        qf[k8][2] = __float_as_uint(__ldg(&Q[qg0 + k8 * 8 + qc + 4]));
        qf[k8][3] = __float_as_uint(__ldg(&Q[qg1 + k8 * 8 + qc + 4]));
    }

    float out[16][4];
    #pragma unroll
    for (int nt = 0; nt < 16; nt++)
        #pragma unroll
        for (int c = 0; c < 4; c++) out[nt][c] = 0.f;

    float m0 = -INFINITY, m1 = -INFINITY, l0 = 0.f, l1 = 0.f;
    const float scale = 0.08838834764831845f;

    for (int kt = 0; kt <= qt; kt++) {
        __syncthreads();
        for (int it = tid; it < BK * 32; it += 128) {
            int r = it >> 5, c4 = (it & 31) << 2;
            size_t base = ((size_t)(b * T_ + kt * BK + r)) * D_MODEL + h * D_HEAD + c4;
            *(float4*)&Ks[r * KPAD + c4] = *(const float4*)&K[base];
            *(float4*)&Vs[r * KPAD + c4] = *(const float4*)&V[base];
        }
        __syncthreads();

        float s[8][4];
        #pragma unroll
        for (int nt = 0; nt < 8; nt++)
            #pragma unroll
            for (int c = 0; c < 4; c++) s[nt][c] = 0.f;

        #pragma unroll
        for (int k8 = 0; k8 < 16; k8++) {
            uint32_t bfrag[8][2];
            #pragma unroll
            for (int nt = 0; nt < 8; nt++) {
                bfrag[nt][0] = __float_as_uint(Ks[(nt * 8 + qr) * KPAD + k8 * 8 + qc]);
                bfrag[nt][1] = __float_as_uint(Ks[(nt * 8 + qr) * KPAD + k8 * 8 + qc + 4]);
            }
            #pragma unroll
            for (int nt = 0; nt < 8; nt++)
                mma_tf32(s[nt], qf[k8], bfrag[nt]);
        }

        const bool diag = (kt == qt);
        #pragma unroll
        for (int nt = 0; nt < 8; nt++) {
            int c0 = nt * 8 + 2 * qc, c1 = c0 + 1;
            if (diag) {
                s[nt][0] = (c0 > rowL0) ? -INFINITY : s[nt][0] * scale;
                s[nt][1] = (c1 > rowL0) ? -INFINITY : s[nt][1] * scale;
                s[nt][2] = (c0 > rowL1) ? -INFINITY : s[nt][2] * scale;
                s[nt][3] = (c1 > rowL1) ? -INFINITY : s[nt][3] * scale;
            } else {
                s[nt][0] *= scale; s[nt][1] *= scale;
                s[nt][2] *= scale; s[nt][3] *= scale;
            }
        }

        float rmax0 = -INFINITY, rmax1 = -INFINITY;
        #pragma unroll
        for (int nt = 0; nt < 8; nt++) {
            rmax0 = fmaxf(rmax0, fmaxf(s[nt][0], s[nt][1]));
            rmax1 = fmaxf(rmax1, fmaxf(s[nt][2], s[nt][3]));
        }
        rmax0 = fmaxf(rmax0, __shfl_xor_sync(0xffffffffu, rmax0, 1));
        rmax0 = fmaxf(rmax0, __shfl_xor_sync(0xffffffffu, rmax0, 2));
        rmax1 = fmaxf(rmax1, __shfl_xor_sync(0xffffffffu, rmax1, 1));
        rmax1 = fmaxf(rmax1, __shfl_xor_sync(0xffffffffu, rmax1, 2));

        float mn0 = fmaxf(m0, rmax0), mn1 = fmaxf(m1, rmax1);
        float a0 = __expf(m0 - mn0),  a1 = __expf(m1 - mn1);

        float sum0 = 0.f, sum1 = 0.f;
        #pragma unroll
        for (int nt = 0; nt < 8; nt++) {
            float p0 = __expf(s[nt][0] - mn0);
            float p1 = __expf(s[nt][1] - mn0);
            float p2 = __expf(s[nt][2] - mn1);
            float p3 = __expf(s[nt][3] - mn1);
            sum0 += p0 + p1; sum1 += p2 + p3;
            *(float2*)&Ps[rowL0 * PPAD + nt * 8 + 2 * qc] = make_float2(p0, p1);
            *(float2*)&Ps[rowL1 * PPAD + nt * 8 + 2 * qc] = make_float2(p2, p3);
        }
        sum0 += __shfl_xor_sync(0xffffffffu, sum0, 1);
        sum0 += __shfl_xor_sync(0xffffffffu, sum0, 2);
        sum1 += __shfl_xor_sync(0xffffffffu, sum1, 1);
        sum1 += __shfl_xor_sync(0xffffffffu, sum1, 2);

        l0 = l0 * a0 + sum0;
        l1 = l1 * a1 + sum1;
        m0 = mn0; m1 = mn1;

        #pragma unroll
        for (int nt = 0; nt < 16; nt++) {
            out[nt][0] *= a0; out[nt][1] *= a0;
            out[nt][2] *= a1; out[nt][3] *= a1;
        }
        __syncwarp();

        #pragma unroll
        for (int k8 = 0; k8 < 8; k8++) {
            uint32_t af[4];
            af[0] = __float_as_uint(Ps[rowL0 * PPAD + k8 * 8 + qc]);
            af[1] = __float_as_uint(Ps[rowL1 * PPAD + k8 * 8 + qc]);
            af[2] = __float_as_uint(Ps[rowL0 * PPAD + k8 * 8 + qc + 4]);
            af[3] = __float_as_uint(Ps[rowL1 * PPAD + k8 * 8 + qc + 4]);
            #pragma unroll
            for (int nt = 0; nt < 16; nt++) {
                uint32_t bf[2];
                bf[0] = __float_as_uint(Vs[(k8 * 8 + qc) * KPAD + nt * 8 + qr]);
                bf[1] = __float_as_uint(Vs[(k8 * 8 + qc + 4) * KPAD + nt * 8 + qr]);
                mma_tf32(out[nt], af, bf);
            }
        }
        __syncwarp();
    }

    float inv0 = 1.f / l0, inv1 = 1.f / l1;
    #pragma unroll
    for (int nt = 0; nt < 16; nt++) {
        int cc = nt * 8 + 2 * qc;
        *(float2*)&O[qg0 + cc] = make_float2(tf32r(out[nt][0] * inv0),
                                             tf32r(out[nt][1] * inv0));
        *(float2*)&O[qg1 + cc] = make_float2(tf32r(out[nt][2] * inv1),
                                             tf32r(out[nt][3] * inv1));
    }
}

// ---------------------------------------------------------------------------
extern "C" void kernel_launch(void* const* d_in, const int* in_sizes, int n_in,
                              void* d_out, int out_size) {
    const float* x  = (const float*)d_in[0];
    const float* rc = (const float*)d_in[1];
    const float* rs = (const float*)d_in[2];
    const float* wq = (const float*)d_in[3];
    const float* wk = (const float*)d_in[4];
    const float* wv = (const float*)d_in[5];
    const float* wo = (const float*)d_in[6];
    float* out = (float*)d_out;

    float *q, *k, *v, *ao, *xt, *wt;
    cudaGetSymbolAddress((void**)&q,  g_q);
    cudaGetSymbolAddress((void**)&k,  g_k);
    cudaGetSymbolAddress((void**)&v,  g_v);
    cudaGetSymbolAddress((void**)&ao, g_ao);
    cudaGetSymbolAddress((void**)&xt, g_xt);
    cudaGetSymbolAddress((void**)&wt, g_wt);

    const int NX = M_TOTAL * D_MODEL;
    const int NW = D_MODEL * D_MODEL;

    cudaFuncSetAttribute(gemm3<1>, cudaFuncAttributeMaxDynamicSharedMemorySize, GEMM_SMEM);
    cudaFuncSetAttribute(gemm3<0>, cudaFuncAttributeMaxDynamicSharedMemorySize, GEMM_SMEM);

    // tf32-round activations + concatenated qkv weights
    to_tf32<<<NX / 1024, 256>>>(x, xt);
    to_tf32<<<NW / 1024, 256>>>(wq, wt);
    to_tf32<<<NW / 1024, 256>>>(wk, wt + NW);
    to_tf32<<<NW / 1024, 256>>>(wv, wt + 2 * NW);

    // fused QKV projection (N = 6144), outputs tf32-rounded
    gemm3<1><<<dim3(3 * D_MODEL / 128, M_TOTAL / 128), 256, GEMM_SMEM>>>(xt, wt, q, k, v);

    int nrope = B_ * T_ * N_HEADS * 64;
    rope_kernel<<<nrope / 256, 256>>>(q, k, rc, rs);

    cudaFuncSetAttribute(attn_tc, cudaFuncAttributeMaxDynamicSharedMemorySize, ATTN_SMEM);
    attn_tc<<<dim3(T_ / BQ, N_HEADS, B_), 128, ATTN_SMEM>>>(q, k, v, ao);

    // output projection (full-precision epilogue)
    to_tf32<<<NW / 1024, 256>>>(wo, wt);
    gemm3<0><<<dim3(D_MODEL / 128, M_TOTAL / 128), 256, GEMM_SMEM>>>(ao, wt, out, out, out);
}

// round 6
// speedup vs baseline: 4.4903x; 1.0256x over previous
#include <cuda_runtime.h>
#include <math.h>
#include <stdint.h>

#define D_MODEL 2048
#define N_HEADS 16
#define D_HEAD  128
#define B_      4
#define T_      2048
#define M_TOTAL (B_*T_)   // 8192

// Scratch: __device__ globals (no allocation allowed in kernel_launch).
__device__ float g_q [B_*T_*D_MODEL];
__device__ float g_k [B_*T_*D_MODEL];
__device__ float g_v [B_*T_*D_MODEL];
__device__ float g_ao[B_*T_*D_MODEL];
__device__ float g_xt[M_TOTAL*D_MODEL];     // tf32-rounded activations
__device__ float g_wt[3*D_MODEL*D_MODEL];   // tf32-rounded weights (qkv concat / wo)

__device__ __forceinline__ float tf32r(float x) {
    uint32_t r;
    asm("cvt.rna.tf32.f32 %0, %1;" : "=r"(r) : "f"(x));
    return __uint_as_float(r);
}

__global__ void to_tf32(const float* __restrict__ in, float* __restrict__ out) {
    int i = (blockIdx.x * blockDim.x + threadIdx.x) * 4;
    float4 v = *(const float4*)(in + i);
    float4 o = make_float4(tf32r(v.x), tf32r(v.y), tf32r(v.z), tf32r(v.w));
    *(float4*)(out + i) = o;
}

#define CP_ASYNC16(dst, src) \
    asm volatile("cp.async.cg.shared.global [%0], [%1], 16;" :: "r"(dst), "l"(src) : "memory")

__device__ __forceinline__ void mma_tf32(float* d, const uint32_t* a, const uint32_t* b) {
    asm volatile(
        "mma.sync.aligned.m16n8k8.row.col.f32.tf32.tf32.f32 "
        "{%0,%1,%2,%3}, {%4,%5,%6,%7}, {%8,%9}, {%0,%1,%2,%3};"
        : "+f"(d[0]), "+f"(d[1]), "+f"(d[2]), "+f"(d[3])
        : "r"(a[0]), "r"(a[1]), "r"(a[2]), "r"(a[3]), "r"(b[0]), "r"(b[1]));
}

// ---------------------------------------------------------------------------
// GEMM v3: Y[M,N] = X[M,K] @ W[N,K]^T.  CTA 128x128, 4 warps, warp tile 64x64,
// CH=32, 3-stage cp.async pipeline, ONE barrier per chunk.
// W has Nglob rows (2048 or 6144); output routed to Yq/Yk/Yv by n block.
// ---------------------------------------------------------------------------
#define CH2   32
#define SROW2 36
#define NST   3
#define STAGE_FLOATS (256 * SROW2)          // A(128 rows) + B(128 rows)
#define STAGE_BYTES  (STAGE_FLOATS * 4)     // 36864
#define BOFF_BYTES   (128 * SROW2 * 4)      // 18432
#define GEMM_SMEM    (NST * STAGE_BYTES)    // 110592
#define NCH2 (D_MODEL / CH2)                // 64

template<int ROUND>
__global__ __launch_bounds__(128, 2) void gemm3(const float* __restrict__ X,
                                                const float* __restrict__ W,
                                                float* __restrict__ Yq,
                                                float* __restrict__ Yk,
                                                float* __restrict__ Yv) {
    extern __shared__ float smd[];
    const uint32_t smem_base = (uint32_t)__cvta_generic_to_shared(smd);

    const int tid  = threadIdx.x;
    const int wid  = tid >> 5;
    const int lane = tid & 31;
    const int qr   = lane >> 2;
    const int qc   = lane & 3;
    const int warpM = wid & 1;      // 2 warps over 128 rows (64 each)
    const int warpN = wid >> 1;     // 2 warps over 128 cols (64 each)

    const int m0      = blockIdx.y * 128;
    const int n_glob  = blockIdx.x * 128;
    const int which   = n_glob >> 11;            // 0,1,2
    const int n0      = n_glob & 2047;
    float* Y = (which == 0) ? Yq : (which == 1) ? Yk : Yv;

    const float* Arow = X + (size_t)m0 * D_MODEL;
    const float* Brow = W + (size_t)n_glob * D_MODEL;

    float acc[4][8][4];
    #pragma unroll
    for (int mt = 0; mt < 4; mt++)
        #pragma unroll
        for (int nt = 0; nt < 8; nt++)
            #pragma unroll
            for (int c = 0; c < 4; c++) acc[mt][nt][c] = 0.f;

    // prefetch: 2048 float4 per chunk, 16 per thread
    auto prefetch = [&](int chunk, int stage) {
        const int k0 = chunk * CH2;
        const uint32_t sbase = smem_base + stage * STAGE_BYTES;
        #pragma unroll
        for (int u = 0; u < 16; u++) {
            int idx = tid + u * 128;
            int isB = idx >> 10;
            int i2  = idx & 1023;
            int row = i2 >> 3;
            int seg = i2 & 7;
            const float* src = (isB ? Brow : Arow) + (size_t)row * D_MODEL + k0 + seg * 4;
            uint32_t dst = sbase + (isB ? BOFF_BYTES : 0) + (row * SROW2 + seg * 4) * 4;
            CP_ASYNC16(dst, src);
        }
    };

    prefetch(0, 0);
    asm volatile("cp.async.commit_group;" ::: "memory");
    prefetch(1, 1);
    asm volatile("cp.async.commit_group;" ::: "memory");

    for (int i = 0; i < NCH2; i++) {
        const int stage = i % NST;
        asm volatile("cp.async.wait_group 1;" ::: "memory");
        __syncthreads();   // sole barrier: proves all warps left stage (i-1)%3

        if (i + 2 < NCH2) prefetch(i + 2, (i + 2) % NST);
        asm volatile("cp.async.commit_group;" ::: "memory");   // may be empty

        const float* Acur = smd + stage * STAGE_FLOATS;
        const float* Bcur = Acur + 128 * SROW2;

        #pragma unroll
        for (int k8 = 0; k8 < CH2; k8 += 8) {
            uint32_t a[4][4], b[8][2];
            #pragma unroll
            for (int mt = 0; mt < 4; mt++) {
                int r = warpM * 64 + mt * 16 + qr;
                a[mt][0] = __float_as_uint(Acur[r * SROW2 + k8 + qc]);
                a[mt][1] = __float_as_uint(Acur[(r + 8) * SROW2 + k8 + qc]);
                a[mt][2] = __float_as_uint(Acur[r * SROW2 + k8 + qc + 4]);
                a[mt][3] = __float_as_uint(Acur[(r + 8) * SROW2 + k8 + qc + 4]);
            }
            #pragma unroll
            for (int nt = 0; nt < 8; nt++) {
                int n = warpN * 64 + nt * 8 + qr;
                b[nt][0] = __float_as_uint(Bcur[n * SROW2 + k8 + qc]);
                b[nt][1] = __float_as_uint(Bcur[n * SROW2 + k8 + qc + 4]);
            }
            #pragma unroll
            for (int mt = 0; mt < 4; mt++)
                #pragma unroll
                for (int nt = 0; nt < 8; nt++)
                    mma_tf32(acc[mt][nt], a[mt], b[nt]);
        }
    }

    #pragma unroll
    for (int mt = 0; mt < 4; mt++) {
        #pragma unroll
        for (int nt = 0; nt < 8; nt++) {
            int r0 = m0 + warpM * 64 + mt * 16 + qr;
            int cc = n0 + warpN * 64 + nt * 8 + qc * 2;
            float o0 = acc[mt][nt][0], o1 = acc[mt][nt][1];
            float o2 = acc[mt][nt][2], o3 = acc[mt][nt][3];
            if (ROUND) { o0 = tf32r(o0); o1 = tf32r(o1); o2 = tf32r(o2); o3 = tf32r(o3); }
            *(float2*)&Y[(size_t)r0 * D_MODEL + cc]       = make_float2(o0, o1);
            *(float2*)&Y[(size_t)(r0 + 8) * D_MODEL + cc] = make_float2(o2, o3);
        }
    }
}

// ---------------------------------------------------------------------------
// RoPE in-place on q and k, writing tf32-rounded results.
// ---------------------------------------------------------------------------
__global__ void rope_kernel(float* __restrict__ q, float* __restrict__ k,
                            const float* __restrict__ cosb,
                            const float* __restrict__ sinb) {
    int idx = blockIdx.x * blockDim.x + threadIdx.x;
    int d = idx & 63;
    int h = (idx >> 6) & (N_HEADS - 1);
    int t = (idx >> 10) & (T_ - 1);
    int b = idx >> 21;
    size_t base = ((size_t)(b * T_ + t) * D_MODEL) + h * D_HEAD;

    float c0 = cosb[t * D_HEAD + d],      s0 = sinb[t * D_HEAD + d];
    float c1 = cosb[t * D_HEAD + d + 64], s1 = sinb[t * D_HEAD + d + 64];

    float q0 = q[base + d], q1 = q[base + d + 64];
    q[base + d]      = tf32r(q0 * c0 - q1 * s0);
    q[base + d + 64] = tf32r(q1 * c1 + q0 * s1);

    float k0 = k[base + d], k1 = k[base + d + 64];
    k[base + d]      = tf32r(k0 * c0 - k1 * s0);
    k[base + d + 64] = tf32r(k1 * c1 + k0 * s1);
}

// ---------------------------------------------------------------------------
// Tensorized flash attention (causal, tf32 mma.sync) — unchanged, passing.
// ---------------------------------------------------------------------------
#define BQ   64
#define BK   64
#define KPAD 132
#define PPAD 68
#define ATTN_SMEM ((2 * BK * KPAD + BQ * PPAD) * 4)

__global__ __launch_bounds__(128) void attn_tc(const float* __restrict__ Q,
                                               const float* __restrict__ K,
                                               const float* __restrict__ V,
                                               float* __restrict__ O) {
    extern __shared__ float smf[];
    float* Ks = smf;
    float* Vs = Ks + BK * KPAD;
    float* Ps = Vs + BK * KPAD;

    const int qt = blockIdx.x, h = blockIdx.y, b = blockIdx.z;
    const int tid  = threadIdx.x;
    const int w    = tid >> 5;
    const int lane = tid & 31;
    const int qr   = lane >> 2;
    const int qc   = lane & 3;

    const int rowL0 = w * 16 + qr;
    const int rowL1 = rowL0 + 8;
    const size_t qg0 = (size_t)(b * T_ + qt * BQ + rowL0) * D_MODEL + h * D_HEAD;
    const size_t qg1 = qg0 + 8 * (size_t)D_MODEL;

    uint32_t qf[16][4];
    #pragma unroll
    for (int k8 = 0; k8 < 16; k8++) {
        qf[k8][0] = __float_as_uint(__ldg(&Q[qg0 + k8 * 8 + qc]));
        qf[k8][1] = __float_as_uint(__ldg(&Q[qg1 + k8 * 8 + qc]));
        qf[k8][2] = __float_as_uint(__ldg(&Q[qg0 + k8 * 8 + qc + 4]));
        qf[k8][3] = __float_as_uint(__ldg(&Q[qg1 + k8 * 8 + qc + 4]));
    }

    float out[16][4];
    #pragma unroll
    for (int nt = 0; nt < 16; nt++)
        #pragma unroll
        for (int c = 0; c < 4; c++) out[nt][c] = 0.f;

    float m0 = -INFINITY, m1 = -INFINITY, l0 = 0.f, l1 = 0.f;
    const float scale = 0.08838834764831845f;

    for (int kt = 0; kt <= qt; kt++) {
        __syncthreads();
        for (int it = tid; it < BK * 32; it += 128) {
            int r = it >> 5, c4 = (it & 31) << 2;
            size_t base = ((size_t)(b * T_ + kt * BK + r)) * D_MODEL + h * D_HEAD + c4;
            *(float4*)&Ks[r * KPAD + c4] = *(const float4*)&K[base];
            *(float4*)&Vs[r * KPAD + c4] = *(const float4*)&V[base];
        }
        __syncthreads();

        float s[8][4];
        #pragma unroll
        for (int nt = 0; nt < 8; nt++)
            #pragma unroll
            for (int c = 0; c < 4; c++) s[nt][c] = 0.f;

        #pragma unroll
        for (int k8 = 0; k8 < 16; k8++) {
            uint32_t bfrag[8][2];
            #pragma unroll
            for (int nt = 0; nt < 8; nt++) {
                bfrag[nt][0] = __float_as_uint(Ks[(nt * 8 + qr) * KPAD + k8 * 8 + qc]);
                bfrag[nt][1] = __float_as_uint(Ks[(nt * 8 + qr) * KPAD + k8 * 8 + qc + 4]);
            }
            #pragma unroll
            for (int nt = 0; nt < 8; nt++)
                mma_tf32(s[nt], qf[k8], bfrag[nt]);
        }

        const bool diag = (kt == qt);
        #pragma unroll
        for (int nt = 0; nt < 8; nt++) {
            int c0 = nt * 8 + 2 * qc, c1 = c0 + 1;
            if (diag) {
                s[nt][0] = (c0 > rowL0) ? -INFINITY : s[nt][0] * scale;
                s[nt][1] = (c1 > rowL0) ? -INFINITY : s[nt][1] * scale;
                s[nt][2] = (c0 > rowL1) ? -INFINITY : s[nt][2] * scale;
                s[nt][3] = (c1 > rowL1) ? -INFINITY : s[nt][3] * scale;
            } else {
                s[nt][0] *= scale; s[nt][1] *= scale;
                s[nt][2] *= scale; s[nt][3] *= scale;
            }
        }

        float rmax0 = -INFINITY, rmax1 = -INFINITY;
        #pragma unroll
        for (int nt = 0; nt < 8; nt++) {
            rmax0 = fmaxf(rmax0, fmaxf(s[nt][0], s[nt][1]));
            rmax1 = fmaxf(rmax1, fmaxf(s[nt][2], s[nt][3]));
        }
        rmax0 = fmaxf(rmax0, __shfl_xor_sync(0xffffffffu, rmax0, 1));
        rmax0 = fmaxf(rmax0, __shfl_xor_sync(0xffffffffu, rmax0, 2));
        rmax1 = fmaxf(rmax1, __shfl_xor_sync(0xffffffffu, rmax1, 1));
        rmax1 = fmaxf(rmax1, __shfl_xor_sync(0xffffffffu, rmax1, 2));

        float mn0 = fmaxf(m0, rmax0), mn1 = fmaxf(m1, rmax1);
        float a0 = __expf(m0 - mn0),  a1 = __expf(m1 - mn1);

        float sum0 = 0.f, sum1 = 0.f;
        #pragma unroll
        for (int nt = 0; nt < 8; nt++) {
            float p0 = __expf(s[nt][0] - mn0);
            float p1 = __expf(s[nt][1] - mn0);
            float p2 = __expf(s[nt][2] - mn1);
            float p3 = __expf(s[nt][3] - mn1);
            sum0 += p0 + p1; sum1 += p2 + p3;
            *(float2*)&Ps[rowL0 * PPAD + nt * 8 + 2 * qc] = make_float2(p0, p1);
            *(float2*)&Ps[rowL1 * PPAD + nt * 8 + 2 * qc] = make_float2(p2, p3);
        }
        sum0 += __shfl_xor_sync(0xffffffffu, sum0, 1);
        sum0 += __shfl_xor_sync(0xffffffffu, sum0, 2);
        sum1 += __shfl_xor_sync(0xffffffffu, sum1, 1);
        sum1 += __shfl_xor_sync(0xffffffffu, sum1, 2);

        l0 = l0 * a0 + sum0;
        l1 = l1 * a1 + sum1;
        m0 = mn0; m1 = mn1;

        #pragma unroll
        for (int nt = 0; nt < 16; nt++) {
            out[nt][0] *= a0; out[nt][1] *= a0;
            out[nt][2] *= a1; out[nt][3] *= a1;
        }
        __syncwarp();

        #pragma unroll
        for (int k8 = 0; k8 < 8; k8++) {
            uint32_t af[4];
            af[0] = __float_as_uint(Ps[rowL0 * PPAD + k8 * 8 + qc]);
            af[1] = __float_as_uint(Ps[rowL1 * PPAD + k8 * 8 + qc]);
            af[2] = __float_as_uint(Ps[rowL0 * PPAD + k8 * 8 + qc + 4]);
            af[3] = __float_as_uint(Ps[rowL1 * PPAD + k8 * 8 + qc + 4]);
            #pragma unroll
            for (int nt = 0; nt < 16; nt++) {
                uint32_t bf[2];
                bf[0] = __float_as_uint(Vs[(k8 * 8 + qc) * KPAD + nt * 8 + qr]);
                bf[1] = __float_as_uint(Vs[(k8 * 8 + qc + 4) * KPAD + nt * 8 + qr]);
                mma_tf32(out[nt], af, bf);
            }
        }
        __syncwarp();
    }

    float inv0 = 1.f / l0, inv1 = 1.f / l1;
    #pragma unroll
    for (int nt = 0; nt < 16; nt++) {
        int cc = nt * 8 + 2 * qc;
        *(float2*)&O[qg0 + cc] = make_float2(tf32r(out[nt][0] * inv0),
                                             tf32r(out[nt][1] * inv0));
        *(float2*)&O[qg1 + cc] = make_float2(tf32r(out[nt][2] * inv1),
                                             tf32r(out[nt][3] * inv1));
    }
}

// ---------------------------------------------------------------------------
extern "C" void kernel_launch(void* const* d_in, const int* in_sizes, int n_in,
                              void* d_out, int out_size) {
    const float* x  = (const float*)d_in[0];
    const float* rc = (const float*)d_in[1];
    const float* rs = (const float*)d_in[2];
    const float* wq = (const float*)d_in[3];
    const float* wk = (const float*)d_in[4];
    const float* wv = (const float*)d_in[5];
    const float* wo = (const float*)d_in[6];
    float* out = (float*)d_out;

    float *q, *k, *v, *ao, *xt, *wt;
    cudaGetSymbolAddress((void**)&q,  g_q);
    cudaGetSymbolAddress((void**)&k,  g_k);
    cudaGetSymbolAddress((void**)&v,  g_v);
    cudaGetSymbolAddress((void**)&ao, g_ao);
    cudaGetSymbolAddress((void**)&xt, g_xt);
    cudaGetSymbolAddress((void**)&wt, g_wt);

    const int NX = M_TOTAL * D_MODEL;
    const int NW = D_MODEL * D_MODEL;

    cudaFuncSetAttribute(gemm3<1>, cudaFuncAttributeMaxDynamicSharedMemorySize, GEMM_SMEM);
    cudaFuncSetAttribute(gemm3<0>, cudaFuncAttributeMaxDynamicSharedMemorySize, GEMM_SMEM);

    // tf32-round activations + concatenated qkv weights
    to_tf32<<<NX / 1024, 256>>>(x, xt);
    to_tf32<<<NW / 1024, 256>>>(wq, wt);
    to_tf32<<<NW / 1024, 256>>>(wk, wt + NW);
    to_tf32<<<NW / 1024, 256>>>(wv, wt + 2 * NW);

    // fused QKV projection (N = 6144), outputs tf32-rounded
    gemm3<1><<<dim3(3 * D_MODEL / 128, M_TOTAL / 128), 128, GEMM_SMEM>>>(xt, wt, q, k, v);

    int nrope = B_ * T_ * N_HEADS * 64;
    rope_kernel<<<nrope / 256, 256>>>(q, k, rc, rs);

    cudaFuncSetAttribute(attn_tc, cudaFuncAttributeMaxDynamicSharedMemorySize, ATTN_SMEM);
    attn_tc<<<dim3(T_ / BQ, N_HEADS, B_), 128, ATTN_SMEM>>>(q, k, v, ao);

    // output projection (full-precision epilogue)
    to_tf32<<<NW / 1024, 256>>>(wo, wt);
    gemm3<0><<<dim3(D_MODEL / 128, M_TOTAL / 128), 128, GEMM_SMEM>>>(ao, wt, out, out, out);
}

// round 7
// speedup vs baseline: 6.4833x; 1.4439x over previous
#include <cuda_runtime.h>
#include <cuda_fp16.h>
#include <math.h>
#include <stdint.h>

#define D_MODEL 2048
#define N_HEADS 16
#define D_HEAD  128
#define B_      4
#define T_      2048
#define M_TOTAL (B_*T_)   // 8192

// Scratch: __device__ globals (no allocation allowed in kernel_launch).
__device__ float  g_q [B_*T_*D_MODEL];
__device__ float  g_k [B_*T_*D_MODEL];
__device__ float  g_v [B_*T_*D_MODEL];
__device__ float  g_ao[B_*T_*D_MODEL];
__device__ __half g_xh[M_TOTAL*D_MODEL];     // fp16 activations
__device__ __half g_wh[3*D_MODEL*D_MODEL];   // fp16 weights (qkv concat / wo)

__device__ __forceinline__ float tf32r(float x) {
    uint32_t r;
    asm("cvt.rna.tf32.f32 %0, %1;" : "=r"(r) : "f"(x));
    return __uint_as_float(r);
}

// fp32 -> fp16 conversion prepass (4 elems/thread)
__global__ void to_f16(const float* __restrict__ in, __half* __restrict__ out) {
    int i = (blockIdx.x * blockDim.x + threadIdx.x) * 4;
    float4 v = *(const float4*)(in + i);
    union { __half2 h[2]; uint2 u; } pk;
    pk.h[0] = __floats2half2_rn(v.x, v.y);
    pk.h[1] = __floats2half2_rn(v.z, v.w);
    *(uint2*)(out + i) = pk.u;
}

#define CP_ASYNC16(dst, src) \
    asm volatile("cp.async.cg.shared.global [%0], [%1], 16;" :: "r"(dst), "l"(src) : "memory")

__device__ __forceinline__ void mma_tf32(float* d, const uint32_t* a, const uint32_t* b) {
    asm volatile(
        "mma.sync.aligned.m16n8k8.row.col.f32.tf32.tf32.f32 "
        "{%0,%1,%2,%3}, {%4,%5,%6,%7}, {%8,%9}, {%0,%1,%2,%3};"
        : "+f"(d[0]), "+f"(d[1]), "+f"(d[2]), "+f"(d[3])
        : "r"(a[0]), "r"(a[1]), "r"(a[2]), "r"(a[3]), "r"(b[0]), "r"(b[1]));
}

__device__ __forceinline__ void mma_f16(float* d, const uint32_t* a, const uint32_t* b) {
    asm volatile(
        "mma.sync.aligned.m16n8k16.row.col.f32.f16.f16.f32 "
        "{%0,%1,%2,%3}, {%4,%5,%6,%7}, {%8,%9}, {%0,%1,%2,%3};"
        : "+f"(d[0]), "+f"(d[1]), "+f"(d[2]), "+f"(d[3])
        : "r"(a[0]), "r"(a[1]), "r"(a[2]), "r"(a[3]), "r"(b[0]), "r"(b[1]));
}

// ---------------------------------------------------------------------------
// GEMM v4 (fp16 HMMA): Y[M,N] = X[M,K] @ W[N,K]^T, fp32 accumulate/output.
// CTA 128x128, 4 warps (warp tile 64x64), K-chunk 64 halves, 3-stage cp.async.
// W has 2048 or 6144 rows; output routed to Yq/Yk/Yv by n block.
// ---------------------------------------------------------------------------
#define CHH    64                           // K halves per chunk (128 B rows)
#define SROWH  72                           // halves per smem row (64 + 8 pad)
#define NSTH   3
#define STAGE_HALVES (256 * SROWH)
#define STAGE_B      (STAGE_HALVES * 2)     // 36864
#define BOFF_B       (128 * SROWH * 2)      // 18432
#define GEMM_SMEM    (NSTH * STAGE_B)       // 110592
#define NCHH  (D_MODEL / CHH)               // 32

template<int ROUND>
__global__ __launch_bounds__(128, 2) void gemm4(const __half* __restrict__ X,
                                                const __half* __restrict__ W,
                                                float* __restrict__ Yq,
                                                float* __restrict__ Yk,
                                                float* __restrict__ Yv) {
    extern __shared__ __half smh[];
    const uint32_t smem_base = (uint32_t)__cvta_generic_to_shared(smh);

    const int tid  = threadIdx.x;
    const int wid  = tid >> 5;
    const int lane = tid & 31;
    const int qr   = lane >> 2;
    const int qc   = lane & 3;
    const int warpM = wid & 1;      // 2 warps over 128 rows
    const int warpN = wid >> 1;     // 2 warps over 128 cols

    const int m0      = blockIdx.y * 128;
    const int n_glob  = blockIdx.x * 128;
    const int which   = n_glob >> 11;
    const int n0      = n_glob & 2047;
    float* Y = (which == 0) ? Yq : (which == 1) ? Yk : Yv;

    const __half* Arow = X + (size_t)m0 * D_MODEL;
    const __half* Brow = W + (size_t)n_glob * D_MODEL;

    float acc[4][8][4];
    #pragma unroll
    for (int mt = 0; mt < 4; mt++)
        #pragma unroll
        for (int nt = 0; nt < 8; nt++)
            #pragma unroll
            for (int c = 0; c < 4; c++) acc[mt][nt][c] = 0.f;

    // prefetch one chunk: 2048 segs of 8 halves (16B), 16 per thread
    auto prefetch = [&](int chunk, int stage) {
        const int k0 = chunk * CHH;
        const uint32_t sbase = smem_base + stage * STAGE_B;
        #pragma unroll
        for (int u = 0; u < 16; u++) {
            int idx = tid + u * 128;
            int isB = idx >> 10;
            int i2  = idx & 1023;
            int row = i2 >> 3;
            int seg = i2 & 7;
            const __half* src = (isB ? Brow : Arow) + (size_t)row * D_MODEL + k0 + seg * 8;
            uint32_t dst = sbase + (isB ? BOFF_B : 0) + row * (SROWH * 2) + seg * 16;
            CP_ASYNC16(dst, src);
        }
    };

    prefetch(0, 0);
    asm volatile("cp.async.commit_group;" ::: "memory");
    prefetch(1, 1);
    asm volatile("cp.async.commit_group;" ::: "memory");

    for (int i = 0; i < NCHH; i++) {
        const int stage = i % NSTH;
        asm volatile("cp.async.wait_group 1;" ::: "memory");
        __syncthreads();

        if (i + 2 < NCHH) prefetch(i + 2, (i + 2) % NSTH);
        asm volatile("cp.async.commit_group;" ::: "memory");

        const __half* Acur = smh + stage * STAGE_HALVES;
        const __half* Bcur = Acur + 128 * SROWH;

        #pragma unroll
        for (int k16 = 0; k16 < CHH; k16 += 16) {
            uint32_t a[4][4], b[8][2];
            #pragma unroll
            for (int mt = 0; mt < 4; mt++) {
                int r = warpM * 64 + mt * 16 + qr;
                a[mt][0] = *(const uint32_t*)&Acur[r * SROWH + k16 + 2 * qc];
                a[mt][1] = *(const uint32_t*)&Acur[(r + 8) * SROWH + k16 + 2 * qc];
                a[mt][2] = *(const uint32_t*)&Acur[r * SROWH + k16 + 8 + 2 * qc];
                a[mt][3] = *(const uint32_t*)&Acur[(r + 8) * SROWH + k16 + 8 + 2 * qc];
            }
            #pragma unroll
            for (int nt = 0; nt < 8; nt++) {
                int n = warpN * 64 + nt * 8 + qr;
                b[nt][0] = *(const uint32_t*)&Bcur[n * SROWH + k16 + 2 * qc];
                b[nt][1] = *(const uint32_t*)&Bcur[n * SROWH + k16 + 8 + 2 * qc];
            }
            #pragma unroll
            for (int mt = 0; mt < 4; mt++)
                #pragma unroll
                for (int nt = 0; nt < 8; nt++)
                    mma_f16(acc[mt][nt], a[mt], b[nt]);
        }
    }

    #pragma unroll
    for (int mt = 0; mt < 4; mt++) {
        #pragma unroll
        for (int nt = 0; nt < 8; nt++) {
            int r0 = m0 + warpM * 64 + mt * 16 + qr;
            int cc = n0 + warpN * 64 + nt * 8 + qc * 2;
            float o0 = acc[mt][nt][0], o1 = acc[mt][nt][1];
            float o2 = acc[mt][nt][2], o3 = acc[mt][nt][3];
            if (ROUND) { o0 = tf32r(o0); o1 = tf32r(o1); o2 = tf32r(o2); o3 = tf32r(o3); }
            *(float2*)&Y[(size_t)r0 * D_MODEL + cc]       = make_float2(o0, o1);
            *(float2*)&Y[(size_t)(r0 + 8) * D_MODEL + cc] = make_float2(o2, o3);
        }
    }
}

// ---------------------------------------------------------------------------
// RoPE in-place on q and k, writing tf32-rounded results.
// ---------------------------------------------------------------------------
__global__ void rope_kernel(float* __restrict__ q, float* __restrict__ k,
                            const float* __restrict__ cosb,
                            const float* __restrict__ sinb) {
    int idx = blockIdx.x * blockDim.x + threadIdx.x;
    int d = idx & 63;
    int h = (idx >> 6) & (N_HEADS - 1);
    int t = (idx >> 10) & (T_ - 1);
    int b = idx >> 21;
    size_t base = ((size_t)(b * T_ + t) * D_MODEL) + h * D_HEAD;

    float c0 = cosb[t * D_HEAD + d],      s0 = sinb[t * D_HEAD + d];
    float c1 = cosb[t * D_HEAD + d + 64], s1 = sinb[t * D_HEAD + d + 64];

    float q0 = q[base + d], q1 = q[base + d + 64];
    q[base + d]      = tf32r(q0 * c0 - q1 * s0);
    q[base + d + 64] = tf32r(q1 * c1 + q0 * s1);

    float k0 = k[base + d], k1 = k[base + d + 64];
    k[base + d]      = tf32r(k0 * c0 - k1 * s0);
    k[base + d + 64] = tf32r(k1 * c1 + k0 * s1);
}

// ---------------------------------------------------------------------------
// Tensorized flash attention (causal, tf32 mma.sync) — unchanged, passing.
// ---------------------------------------------------------------------------
#define BQ   64
#define BK   64
#define KPAD 132
#define PPAD 68
#define ATTN_SMEM ((2 * BK * KPAD + BQ * PPAD) * 4)

__global__ __launch_bounds__(128) void attn_tc(const float* __restrict__ Q,
                                               const float* __restrict__ K,
                                               const float* __restrict__ V,
                                               float* __restrict__ O) {
    extern __shared__ float smf[];
    float* Ks = smf;
    float* Vs = Ks + BK * KPAD;
    float* Ps = Vs + BK * KPAD;

    const int qt = blockIdx.x, h = blockIdx.y, b = blockIdx.z;
    const int tid  = threadIdx.x;
    const int w    = tid >> 5;
    const int lane = tid & 31;
    const int qr   = lane >> 2;
    const int qc   = lane & 3;

    const int rowL0 = w * 16 + qr;
    const int rowL1 = rowL0 + 8;
    const size_t qg0 = (size_t)(b * T_ + qt * BQ + rowL0) * D_MODEL + h * D_HEAD;
    const size_t qg1 = qg0 + 8 * (size_t)D_MODEL;

    uint32_t qf[16][4];
    #pragma unroll
    for (int k8 = 0; k8 < 16; k8++) {
        qf[k8][0] = __float_as_uint(__ldg(&Q[qg0 + k8 * 8 + qc]));
        qf[k8][1] = __float_as_uint(__ldg(&Q[qg1 + k8 * 8 + qc]));
        qf[k8][2] = __float_as_uint(__ldg(&Q[qg0 + k8 * 8 + qc + 4]));
        qf[k8][3] = __float_as_uint(__ldg(&Q[qg1 + k8 * 8 + qc + 4]));
    }

    float out[16][4];
    #pragma unroll
    for (int nt = 0; nt < 16; nt++)
        #pragma unroll
        for (int c = 0; c < 4; c++) out[nt][c] = 0.f;

    float m0 = -INFINITY, m1 = -INFINITY, l0 = 0.f, l1 = 0.f;
    const float scale = 0.08838834764831845f;

    for (int kt = 0; kt <= qt; kt++) {
        __syncthreads();
        for (int it = tid; it < BK * 32; it += 128) {
            int r = it >> 5, c4 = (it & 31) << 2;
            size_t base = ((size_t)(b * T_ + kt * BK + r)) * D_MODEL + h * D_HEAD + c4;
            *(float4*)&Ks[r * KPAD + c4] = *(const float4*)&K[base];
            *(float4*)&Vs[r * KPAD + c4] = *(const float4*)&V[base];
        }
        __syncthreads();

        float s[8][4];
        #pragma unroll
        for (int nt = 0; nt < 8; nt++)
            #pragma unroll
            for (int c = 0; c < 4; c++) s[nt][c] = 0.f;

        #pragma unroll
        for (int k8 = 0; k8 < 16; k8++) {
            uint32_t bfrag[8][2];
            #pragma unroll
            for (int nt = 0; nt < 8; nt++) {
                bfrag[nt][0] = __float_as_uint(Ks[(nt * 8 + qr) * KPAD + k8 * 8 + qc]);
                bfrag[nt][1] = __float_as_uint(Ks[(nt * 8 + qr) * KPAD + k8 * 8 + qc + 4]);
            }
            #pragma unroll
            for (int nt = 0; nt < 8; nt++)
                mma_tf32(s[nt], qf[k8], bfrag[nt]);
        }

        const bool diag = (kt == qt);
        #pragma unroll
        for (int nt = 0; nt < 8; nt++) {
            int c0 = nt * 8 + 2 * qc, c1 = c0 + 1;
            if (diag) {
                s[nt][0] = (c0 > rowL0) ? -INFINITY : s[nt][0] * scale;
                s[nt][1] = (c1 > rowL0) ? -INFINITY : s[nt][1] * scale;
                s[nt][2] = (c0 > rowL1) ? -INFINITY : s[nt][2] * scale;
                s[nt][3] = (c1 > rowL1) ? -INFINITY : s[nt][3] * scale;
            } else {
                s[nt][0] *= scale; s[nt][1] *= scale;
                s[nt][2] *= scale; s[nt][3] *= scale;
            }
        }

        float rmax0 = -INFINITY, rmax1 = -INFINITY;
        #pragma unroll
        for (int nt = 0; nt < 8; nt++) {
            rmax0 = fmaxf(rmax0, fmaxf(s[nt][0], s[nt][1]));
            rmax1 = fmaxf(rmax1, fmaxf(s[nt][2], s[nt][3]));
        }
        rmax0 = fmaxf(rmax0, __shfl_xor_sync(0xffffffffu, rmax0, 1));
        rmax0 = fmaxf(rmax0, __shfl_xor_sync(0xffffffffu, rmax0, 2));
        rmax1 = fmaxf(rmax1, __shfl_xor_sync(0xffffffffu, rmax1, 1));
        rmax1 = fmaxf(rmax1, __shfl_xor_sync(0xffffffffu, rmax1, 2));

        float mn0 = fmaxf(m0, rmax0), mn1 = fmaxf(m1, rmax1);
        float a0 = __expf(m0 - mn0),  a1 = __expf(m1 - mn1);

        float sum0 = 0.f, sum1 = 0.f;
        #pragma unroll
        for (int nt = 0; nt < 8; nt++) {
            float p0 = __expf(s[nt][0] - mn0);
            float p1 = __expf(s[nt][1] - mn0);
            float p2 = __expf(s[nt][2] - mn1);
            float p3 = __expf(s[nt][3] - mn1);
            sum0 += p0 + p1; sum1 += p2 + p3;
            *(float2*)&Ps[rowL0 * PPAD + nt * 8 + 2 * qc] = make_float2(p0, p1);
            *(float2*)&Ps[rowL1 * PPAD + nt * 8 + 2 * qc] = make_float2(p2, p3);
        }
        sum0 += __shfl_xor_sync(0xffffffffu, sum0, 1);
        sum0 += __shfl_xor_sync(0xffffffffu, sum0, 2);
        sum1 += __shfl_xor_sync(0xffffffffu, sum1, 1);
        sum1 += __shfl_xor_sync(0xffffffffu, sum1, 2);

        l0 = l0 * a0 + sum0;
        l1 = l1 * a1 + sum1;
        m0 = mn0; m1 = mn1;

        #pragma unroll
        for (int nt = 0; nt < 16; nt++) {
            out[nt][0] *= a0; out[nt][1] *= a0;
            out[nt][2] *= a1; out[nt][3] *= a1;
        }
        __syncwarp();

        #pragma unroll
        for (int k8 = 0; k8 < 8; k8++) {
            uint32_t af[4];
            af[0] = __float_as_uint(Ps[rowL0 * PPAD + k8 * 8 + qc]);
            af[1] = __float_as_uint(Ps[rowL1 * PPAD + k8 * 8 + qc]);
            af[2] = __float_as_uint(Ps[rowL0 * PPAD + k8 * 8 + qc + 4]);
            af[3] = __float_as_uint(Ps[rowL1 * PPAD + k8 * 8 + qc + 4]);
            #pragma unroll
            for (int nt = 0; nt < 16; nt++) {
                uint32_t bf[2];
                bf[0] = __float_as_uint(Vs[(k8 * 8 + qc) * KPAD + nt * 8 + qr]);
                bf[1] = __float_as_uint(Vs[(k8 * 8 + qc + 4) * KPAD + nt * 8 + qr]);
                mma_tf32(out[nt], af, bf);
            }
        }
        __syncwarp();
    }

    float inv0 = 1.f / l0, inv1 = 1.f / l1;
    #pragma unroll
    for (int nt = 0; nt < 16; nt++) {
        int cc = nt * 8 + 2 * qc;
        *(float2*)&O[qg0 + cc] = make_float2(tf32r(out[nt][0] * inv0),
                                             tf32r(out[nt][1] * inv0));
        *(float2*)&O[qg1 + cc] = make_float2(tf32r(out[nt][2] * inv1),
                                             tf32r(out[nt][3] * inv1));
    }
}

// ---------------------------------------------------------------------------
extern "C" void kernel_launch(void* const* d_in, const int* in_sizes, int n_in,
                              void* d_out, int out_size) {
    const float* x  = (const float*)d_in[0];
    const float* rc = (const float*)d_in[1];
    const float* rs = (const float*)d_in[2];
    const float* wq = (const float*)d_in[3];
    const float* wk = (const float*)d_in[4];
    const float* wv = (const float*)d_in[5];
    const float* wo = (const float*)d_in[6];
    float* out = (float*)d_out;

    float *q, *k, *v, *ao;
    __half *xh, *wh;
    cudaGetSymbolAddress((void**)&q,  g_q);
    cudaGetSymbolAddress((void**)&k,  g_k);
    cudaGetSymbolAddress((void**)&v,  g_v);
    cudaGetSymbolAddress((void**)&ao, g_ao);
    cudaGetSymbolAddress((void**)&xh, g_xh);
    cudaGetSymbolAddress((void**)&wh, g_wh);

    const int NX = M_TOTAL * D_MODEL;
    const int NW = D_MODEL * D_MODEL;

    cudaFuncSetAttribute(gemm4<1>, cudaFuncAttributeMaxDynamicSharedMemorySize, GEMM_SMEM);
    cudaFuncSetAttribute(gemm4<0>, cudaFuncAttributeMaxDynamicSharedMemorySize, GEMM_SMEM);

    // fp16 conversion of activations + concatenated qkv weights
    to_f16<<<NX / 1024, 256>>>(x, xh);
    to_f16<<<NW / 1024, 256>>>(wq, wh);
    to_f16<<<NW / 1024, 256>>>(wk, wh + NW);
    to_f16<<<NW / 1024, 256>>>(wv, wh + 2 * NW);

    // fused QKV projection (N = 6144), fp32 outputs tf32-rounded for attn
    gemm4<1><<<dim3(3 * D_MODEL / 128, M_TOTAL / 128), 128, GEMM_SMEM>>>(xh, wh, q, k, v);

    int nrope = B_ * T_ * N_HEADS * 64;
    rope_kernel<<<nrope / 256, 256>>>(q, k, rc, rs);

    cudaFuncSetAttribute(attn_tc, cudaFuncAttributeMaxDynamicSharedMemorySize, ATTN_SMEM);
    attn_tc<<<dim3(T_ / BQ, N_HEADS, B_), 128, ATTN_SMEM>>>(q, k, v, ao);

    // output projection: convert ao + wo to fp16, full-precision fp32 result
    to_f16<<<NX / 1024, 256>>>(ao, xh);
    to_f16<<<NW / 1024, 256>>>(wo, wh);
    gemm4<0><<<dim3(D_MODEL / 128, M_TOTAL / 128), 128, GEMM_SMEM>>>(xh, wh, out, out, out);
}

// round 8
// speedup vs baseline: 8.9666x; 1.3830x over previous
#include <cuda_runtime.h>
#include <cuda_fp16.h>
#include <math.h>
#include <stdint.h>

#define D_MODEL 2048
#define N_HEADS 16
#define D_HEAD  128
#define B_      4
#define T_      2048
#define M_TOTAL (B_*T_)   // 8192

// Scratch: __device__ globals (no allocation allowed in kernel_launch).
__device__ __half g_qh[M_TOTAL*D_MODEL];     // fp16 q (rope'd)
__device__ __half g_kh[M_TOTAL*D_MODEL];     // fp16 k (rope'd)
__device__ __half g_vt[M_TOTAL*D_MODEL];     // fp16 v, transposed [b,h][d][t]
__device__ __half g_xh[M_TOTAL*D_MODEL];     // fp16 activations (x, then attn-out)
__device__ __half g_wh[3*D_MODEL*D_MODEL];   // fp16 weights (qkv concat / wo)

__device__ __forceinline__ uint32_t packh2(float a, float b) {
    __half2 h = __floats2half2_rn(a, b);
    return *(uint32_t*)&h;
}

// fp32 -> fp16 conversion prepass (4 elems/thread)
__global__ void to_f16(const float* __restrict__ in, __half* __restrict__ out) {
    int i = (blockIdx.x * blockDim.x + threadIdx.x) * 4;
    float4 v = *(const float4*)(in + i);
    uint2 pk;
    pk.x = packh2(v.x, v.y);
    pk.y = packh2(v.z, v.w);
    *(uint2*)(out + i) = pk;
}

#define CP_ASYNC16(dst, src) \
    asm volatile("cp.async.cg.shared.global [%0], [%1], 16;" :: "r"(dst), "l"(src) : "memory")

__device__ __forceinline__ void mma_f16(float* d, const uint32_t* a, const uint32_t* b) {
    asm volatile(
        "mma.sync.aligned.m16n8k16.row.col.f32.f16.f16.f32 "
        "{%0,%1,%2,%3}, {%4,%5,%6,%7}, {%8,%9}, {%0,%1,%2,%3};"
        : "+f"(d[0]), "+f"(d[1]), "+f"(d[2]), "+f"(d[3])
        : "r"(a[0]), "r"(a[1]), "r"(a[2]), "r"(a[3]), "r"(b[0]), "r"(b[1]));
}

// ---------------------------------------------------------------------------
// GEMM (fp16 HMMA): Y = X @ W^T.  CTA 128x128, 4 warps (64x64), 3-stage.
// EPI=1: QKV — write fp16 q/k rows, v transposed [b,h][d][t].
// EPI=0: write fp32 to Yf.
// ---------------------------------------------------------------------------
#define CHH    64
#define SROWH  72
#define NSTH   3
#define STAGE_HALVES (256 * SROWH)
#define STAGE_B      (STAGE_HALVES * 2)
#define BOFF_B       (128 * SROWH * 2)
#define GEMM_SMEM    (NSTH * STAGE_B)       // 110592
#define NCHH  (D_MODEL / CHH)               // 32

template<int EPI>
__global__ __launch_bounds__(128, 2) void gemm5(const __half* __restrict__ X,
                                                const __half* __restrict__ W,
                                                __half* __restrict__ Yq,
                                                __half* __restrict__ Yk,
                                                __half* __restrict__ Yvt,
                                                float* __restrict__ Yf) {
    extern __shared__ __half smh[];
    const uint32_t smem_base = (uint32_t)__cvta_generic_to_shared(smh);

    const int tid  = threadIdx.x;
    const int wid  = tid >> 5;
    const int lane = tid & 31;
    const int qr   = lane >> 2;
    const int qc   = lane & 3;
    const int warpM = wid & 1;
    const int warpN = wid >> 1;

    const int m0      = blockIdx.y * 128;
    const int n_glob  = blockIdx.x * 128;
    const int which   = n_glob >> 11;
    const int n0      = n_glob & 2047;

    const __half* Arow = X + (size_t)m0 * D_MODEL;
    const __half* Brow = W + (size_t)n_glob * D_MODEL;

    float acc[4][8][4];
    #pragma unroll
    for (int mt = 0; mt < 4; mt++)
        #pragma unroll
        for (int nt = 0; nt < 8; nt++)
            #pragma unroll
            for (int c = 0; c < 4; c++) acc[mt][nt][c] = 0.f;

    auto prefetch = [&](int chunk, int stage) {
        const int k0 = chunk * CHH;
        const uint32_t sbase = smem_base + stage * STAGE_B;
        #pragma unroll
        for (int u = 0; u < 16; u++) {
            int idx = tid + u * 128;
            int isB = idx >> 10;
            int i2  = idx & 1023;
            int row = i2 >> 3;
            int seg = i2 & 7;
            const __half* src = (isB ? Brow : Arow) + (size_t)row * D_MODEL + k0 + seg * 8;
            uint32_t dst = sbase + (isB ? BOFF_B : 0) + row * (SROWH * 2) + seg * 16;
            CP_ASYNC16(dst, src);
        }
    };

    prefetch(0, 0);
    asm volatile("cp.async.commit_group;" ::: "memory");
    prefetch(1, 1);
    asm volatile("cp.async.commit_group;" ::: "memory");

    for (int i = 0; i < NCHH; i++) {
        const int stage = i % NSTH;
        asm volatile("cp.async.wait_group 1;" ::: "memory");
        __syncthreads();

        if (i + 2 < NCHH) prefetch(i + 2, (i + 2) % NSTH);
        asm volatile("cp.async.commit_group;" ::: "memory");

        const __half* Acur = smh + stage * STAGE_HALVES;
        const __half* Bcur = Acur + 128 * SROWH;

        #pragma unroll
        for (int k16 = 0; k16 < CHH; k16 += 16) {
            uint32_t a[4][4], b[8][2];
            #pragma unroll
            for (int mt = 0; mt < 4; mt++) {
                int r = warpM * 64 + mt * 16 + qr;
                a[mt][0] = *(const uint32_t*)&Acur[r * SROWH + k16 + 2 * qc];
                a[mt][1] = *(const uint32_t*)&Acur[(r + 8) * SROWH + k16 + 2 * qc];
                a[mt][2] = *(const uint32_t*)&Acur[r * SROWH + k16 + 8 + 2 * qc];
                a[mt][3] = *(const uint32_t*)&Acur[(r + 8) * SROWH + k16 + 8 + 2 * qc];
            }
            #pragma unroll
            for (int nt = 0; nt < 8; nt++) {
                int n = warpN * 64 + nt * 8 + qr;
                b[nt][0] = *(const uint32_t*)&Bcur[n * SROWH + k16 + 2 * qc];
                b[nt][1] = *(const uint32_t*)&Bcur[n * SROWH + k16 + 8 + 2 * qc];
            }
            #pragma unroll
            for (int mt = 0; mt < 4; mt++)
                #pragma unroll
                for (int nt = 0; nt < 8; nt++)
                    mma_f16(acc[mt][nt], a[mt], b[nt]);
        }
    }

    #pragma unroll
    for (int mt = 0; mt < 4; mt++) {
        #pragma unroll
        for (int nt = 0; nt < 8; nt++) {
            int r0 = m0 + warpM * 64 + mt * 16 + qr;
            int cc = n0 + warpN * 64 + nt * 8 + qc * 2;
            float o0 = acc[mt][nt][0], o1 = acc[mt][nt][1];
            float o2 = acc[mt][nt][2], o3 = acc[mt][nt][3];
            if (EPI == 0) {
                *(float2*)&Yf[(size_t)r0 * D_MODEL + cc]       = make_float2(o0, o1);
                *(float2*)&Yf[(size_t)(r0 + 8) * D_MODEL + cc] = make_float2(o2, o3);
            } else if (which < 2) {
                __half* Yh = (which == 0) ? Yq : Yk;
                *(uint32_t*)&Yh[(size_t)r0 * D_MODEL + cc]       = packh2(o0, o1);
                *(uint32_t*)&Yh[(size_t)(r0 + 8) * D_MODEL + cc] = packh2(o2, o3);
            } else {
                // v transposed: [b,h][d][t]
                int hh = cc >> 7, d = cc & 127;
                int bb = r0 >> 11, tt = r0 & 2047;
                size_t base = ((size_t)(bb * N_HEADS + hh) * D_HEAD + d) * T_ + tt;
                Yvt[base]          = __float2half_rn(o0);
                Yvt[base + T_]     = __float2half_rn(o1);   // d+1
                Yvt[base + 8]      = __float2half_rn(o2);   // t+8
                Yvt[base + T_ + 8] = __float2half_rn(o3);
            }
        }
    }
}

// ---------------------------------------------------------------------------
// RoPE in-place on fp16 q and k.  Pair (d, d+64) per head.
// ---------------------------------------------------------------------------
__global__ void rope_kernel(__half* __restrict__ q, __half* __restrict__ k,
                            const float* __restrict__ cosb,
                            const float* __restrict__ sinb) {
    int idx = blockIdx.x * blockDim.x + threadIdx.x;
    int d = idx & 63;
    int h = (idx >> 6) & (N_HEADS - 1);
    int t = (idx >> 10) & (T_ - 1);
    int b = idx >> 21;
    size_t base = ((size_t)(b * T_ + t) * D_MODEL) + h * D_HEAD;

    float c0 = cosb[t * D_HEAD + d],      s0 = sinb[t * D_HEAD + d];
    float c1 = cosb[t * D_HEAD + d + 64], s1 = sinb[t * D_HEAD + d + 64];

    float q0 = __half2float(q[base + d]), q1 = __half2float(q[base + d + 64]);
    q[base + d]      = __float2half_rn(q0 * c0 - q1 * s0);
    q[base + d + 64] = __float2half_rn(q1 * c1 + q0 * s1);

    float k0 = __half2float(k[base + d]), k1 = __half2float(k[base + d + 64]);
    k[base + d]      = __float2half_rn(k0 * c0 - k1 * s0);
    k[base + d + 64] = __float2half_rn(k1 * c1 + k0 * s1);
}

// ---------------------------------------------------------------------------
// fp16 flash attention (causal, m16n8k16).  Block (qt,h,b), 4 warps,
// warp owns 16 q-rows.  P stays in registers (C->A fragment identity).
// ---------------------------------------------------------------------------
#define BQ    64
#define BK    64
#define KPADH 136    // halves per Ks row (128 + 8)
#define VPADH 72     // halves per Vst row (64 + 8)

__global__ __launch_bounds__(128) void attn_f16(const __half* __restrict__ Q,
                                                const __half* __restrict__ K,
                                                const __half* __restrict__ vT,
                                                __half* __restrict__ O) {
    __shared__ __half Ks [BK * KPADH];      // [key][dim]
    __shared__ __half Vst[D_HEAD * VPADH];  // [dim][key]

    const int qt = blockIdx.x, h = blockIdx.y, b = blockIdx.z;
    const int tid  = threadIdx.x;
    const int w    = tid >> 5;
    const int lane = tid & 31;
    const int qr   = lane >> 2;
    const int qc   = lane & 3;

    const int rowL0 = w * 16 + qr;
    const int rowL1 = rowL0 + 8;
    const size_t qg0 = (size_t)(b * T_ + qt * BQ + rowL0) * D_MODEL + h * D_HEAD;
    const size_t qg1 = qg0 + 8 * (size_t)D_MODEL;

    // Q A-fragments: 8 k16-steps x 4 regs (half2 each)
    uint32_t qf[8][4];
    #pragma unroll
    for (int j = 0; j < 8; j++) {
        qf[j][0] = *(const uint32_t*)&Q[qg0 + j * 16 + 2 * qc];
        qf[j][1] = *(const uint32_t*)&Q[qg1 + j * 16 + 2 * qc];
        qf[j][2] = *(const uint32_t*)&Q[qg0 + j * 16 + 8 + 2 * qc];
        qf[j][3] = *(const uint32_t*)&Q[qg1 + j * 16 + 8 + 2 * qc];
    }

    float out[16][4];
    #pragma unroll
    for (int nt = 0; nt < 16; nt++)
        #pragma unroll
        for (int c = 0; c < 4; c++) out[nt][c] = 0.f;

    float m0 = -INFINITY, m1 = -INFINITY, l0 = 0.f, l1 = 0.f;
    const float scale = 0.08838834764831845f;

    const __half* vbase = vT + (size_t)(b * N_HEADS + h) * D_HEAD * T_;

    for (int kt = 0; kt <= qt; kt++) {
        __syncthreads();
        // K tile: 64 rows x 128 halves (uint4 = 8 halves)
        #pragma unroll
        for (int u = 0; u < 8; u++) {
            int it = tid + u * 128;
            int r = it >> 4, seg = it & 15;
            *(uint4*)&Ks[r * KPADH + seg * 8] =
                *(const uint4*)&K[(size_t)(b * T_ + kt * BK + r) * D_MODEL + h * D_HEAD + seg * 8];
        }
        // V^T tile: 128 rows x 64 halves
        #pragma unroll
        for (int u = 0; u < 8; u++) {
            int it = tid + u * 128;
            int d = it >> 3, seg = it & 7;
            *(uint4*)&Vst[d * VPADH + seg * 8] =
                *(const uint4*)&vbase[(size_t)d * T_ + kt * BK + seg * 8];
        }
        __syncthreads();

        // S = Q @ K^T
        float s[8][4];
        #pragma unroll
        for (int nt = 0; nt < 8; nt++)
            #pragma unroll
            for (int c = 0; c < 4; c++) s[nt][c] = 0.f;

        #pragma unroll
        for (int j = 0; j < 8; j++) {
            #pragma unroll
            for (int nt = 0; nt < 8; nt++) {
                uint32_t bf[2];
                bf[0] = *(const uint32_t*)&Ks[(nt * 8 + qr) * KPADH + j * 16 + 2 * qc];
                bf[1] = *(const uint32_t*)&Ks[(nt * 8 + qr) * KPADH + j * 16 + 8 + 2 * qc];
                mma_f16(s[nt], qf[j], bf);
            }
        }

        // scale + causal mask
        const bool diag = (kt == qt);
        #pragma unroll
        for (int nt = 0; nt < 8; nt++) {
            int c0 = nt * 8 + 2 * qc, c1 = c0 + 1;
            if (diag) {
                s[nt][0] = (c0 > rowL0) ? -INFINITY : s[nt][0] * scale;
                s[nt][1] = (c1 > rowL0) ? -INFINITY : s[nt][1] * scale;
                s[nt][2] = (c0 > rowL1) ? -INFINITY : s[nt][2] * scale;
                s[nt][3] = (c1 > rowL1) ? -INFINITY : s[nt][3] * scale;
            } else {
                s[nt][0] *= scale; s[nt][1] *= scale;
                s[nt][2] *= scale; s[nt][3] *= scale;
            }
        }

        // online softmax (rows qr / qr+8)
        float rmax0 = -INFINITY, rmax1 = -INFINITY;
        #pragma unroll
        for (int nt = 0; nt < 8; nt++) {
            rmax0 = fmaxf(rmax0, fmaxf(s[nt][0], s[nt][1]));
            rmax1 = fmaxf(rmax1, fmaxf(s[nt][2], s[nt][3]));
        }
        rmax0 = fmaxf(rmax0, __shfl_xor_sync(0xffffffffu, rmax0, 1));
        rmax0 = fmaxf(rmax0, __shfl_xor_sync(0xffffffffu, rmax0, 2));
        rmax1 = fmaxf(rmax1, __shfl_xor_sync(0xffffffffu, rmax1, 1));
        rmax1 = fmaxf(rmax1, __shfl_xor_sync(0xffffffffu, rmax1, 2));

        float mn0 = fmaxf(m0, rmax0), mn1 = fmaxf(m1, rmax1);
        float a0 = __expf(m0 - mn0),  a1 = __expf(m1 - mn1);

        // exp + pack P into A-fragments (pr0: row qr pair; pr1: row qr+8 pair)
        uint32_t pr0[8], pr1[8];
        float sum0 = 0.f, sum1 = 0.f;
        #pragma unroll
        for (int nt = 0; nt < 8; nt++) {
            float p0 = __expf(s[nt][0] - mn0);
            float p1 = __expf(s[nt][1] - mn0);
            float p2 = __expf(s[nt][2] - mn1);
            float p3 = __expf(s[nt][3] - mn1);
            sum0 += p0 + p1; sum1 += p2 + p3;
            pr0[nt] = packh2(p0, p1);
            pr1[nt] = packh2(p2, p3);
        }
        sum0 += __shfl_xor_sync(0xffffffffu, sum0, 1);
        sum0 += __shfl_xor_sync(0xffffffffu, sum0, 2);
        sum1 += __shfl_xor_sync(0xffffffffu, sum1, 1);
        sum1 += __shfl_xor_sync(0xffffffffu, sum1, 2);

        l0 = l0 * a0 + sum0;
        l1 = l1 * a1 + sum1;
        m0 = mn0; m1 = mn1;

        #pragma unroll
        for (int nt = 0; nt < 16; nt++) {
            out[nt][0] *= a0; out[nt][1] *= a0;
            out[nt][2] *= a1; out[nt][3] *= a1;
        }

        // out += P @ V   (P direct from registers; V^T fragments from smem)
        #pragma unroll
        for (int j = 0; j < 4; j++) {
            uint32_t af[4] = { pr0[2 * j], pr1[2 * j], pr0[2 * j + 1], pr1[2 * j + 1] };
            #pragma unroll
            for (int nt = 0; nt < 16; nt++) {
                uint32_t bf[2];
                bf[0] = *(const uint32_t*)&Vst[(nt * 8 + qr) * VPADH + j * 16 + 2 * qc];
                bf[1] = *(const uint32_t*)&Vst[(nt * 8 + qr) * VPADH + j * 16 + 8 + 2 * qc];
                mma_f16(out[nt], af, bf);
            }
        }
    }

    // normalize + store fp16 (feeds final GEMM directly)
    float inv0 = 1.f / l0, inv1 = 1.f / l1;
    #pragma unroll
    for (int nt = 0; nt < 16; nt++) {
        int cc = nt * 8 + 2 * qc;
        *(uint32_t*)&O[qg0 + cc] = packh2(out[nt][0] * inv0, out[nt][1] * inv0);
        *(uint32_t*)&O[qg1 + cc] = packh2(out[nt][2] * inv1, out[nt][3] * inv1);
    }
}

// ---------------------------------------------------------------------------
extern "C" void kernel_launch(void* const* d_in, const int* in_sizes, int n_in,
                              void* d_out, int out_size) {
    const float* x  = (const float*)d_in[0];
    const float* rc = (const float*)d_in[1];
    const float* rs = (const float*)d_in[2];
    const float* wq = (const float*)d_in[3];
    const float* wk = (const float*)d_in[4];
    const float* wv = (const float*)d_in[5];
    const float* wo = (const float*)d_in[6];
    float* out = (float*)d_out;

    __half *qh, *kh, *vt, *xh, *wh;
    cudaGetSymbolAddress((void**)&qh, g_qh);
    cudaGetSymbolAddress((void**)&kh, g_kh);
    cudaGetSymbolAddress((void**)&vt, g_vt);
    cudaGetSymbolAddress((void**)&xh, g_xh);
    cudaGetSymbolAddress((void**)&wh, g_wh);

    const int NX = M_TOTAL * D_MODEL;
    const int NW = D_MODEL * D_MODEL;

    cudaFuncSetAttribute(gemm5<1>, cudaFuncAttributeMaxDynamicSharedMemorySize, GEMM_SMEM);
    cudaFuncSetAttribute(gemm5<0>, cudaFuncAttributeMaxDynamicSharedMemorySize, GEMM_SMEM);

    // fp16 conversion of activations + concatenated qkv weights
    to_f16<<<NX / 1024, 256>>>(x, xh);
    to_f16<<<NW / 1024, 256>>>(wq, wh);
    to_f16<<<NW / 1024, 256>>>(wk, wh + NW);
    to_f16<<<NW / 1024, 256>>>(wv, wh + 2 * NW);

    // fused QKV projection (N = 6144): q/k fp16 rows, v fp16 transposed
    gemm5<1><<<dim3(3 * D_MODEL / 128, M_TOTAL / 128), 128, GEMM_SMEM>>>(
        xh, wh, qh, kh, vt, nullptr);

    int nrope = B_ * T_ * N_HEADS * 64;
    rope_kernel<<<nrope / 256, 256>>>(qh, kh, rc, rs);

    // fp16 attention; writes fp16 attn-out straight into xh
    attn_f16<<<dim3(T_ / BQ, N_HEADS, B_), 128>>>(qh, kh, vt, xh);

    // output projection: fp32 result
    to_f16<<<NW / 1024, 256>>>(wo, wh);
    gemm5<0><<<dim3(D_MODEL / 128, M_TOTAL / 128), 128, GEMM_SMEM>>>(
        xh, wh, nullptr, nullptr, nullptr, out);
}